// round 3
// baseline (speedup 1.0000x reference)
#include <cuda_runtime.h>
#include <math.h>

#define FD 128
#define RD 64
#define BM 64
#define BN 128
#define NT 128
#define NMAX 8192

// Scratch (device globals -- no runtime allocation allowed)
__device__ float g_S [NMAX*RD];
__device__ float g_bg[NMAX*FD];
__device__ float g_bh[NMAX*FD];
__device__ float g_bx[NMAX*FD];
__device__ float g_bt[NMAX*FD];
__device__ float g_fa[NMAX*FD];
__device__ float g_fb[NMAX*FD];

// shifted softplus: log1p(exp(x)) - ln2, numerically stable
__device__ __forceinline__ float sspf(float x){
    return fmaxf(x, 0.0f) + log1pf(__expf(-fabsf(x))) - 0.6931471805599453f;
}

__global__ void zero_kernel(float* __restrict__ p, int n){
    int i = blockIdx.x * blockDim.x + threadIdx.x;
    if (i < n) p[i] = 0.0f;
}

// S[atom] += radial[pair]  for each of the 2*P (side,pair) entries.
// One thread handles one float4 chunk of one entry. float4 atomicAdd (cc>=9.0)
// -> RED.E.ADD.F32 .128, 4x fewer atomic ops.
__global__ void scatter_kernel(const float* __restrict__ radial,
                               const int*   __restrict__ idx,
                               float* __restrict__ S, int P){
    int gid = blockIdx.x * blockDim.x + threadIdx.x;
    int total = 2 * P * (RD/4);
    if (gid >= total) return;
    int c = gid & 15;        // RD/4 == 16 chunks
    int e = gid >> 4;        // entry in [0, 2P)
    int atom = idx[e];
    int row  = (e < P) ? e : (e - P);
    float4 v = *reinterpret_cast<const float4*>(radial + (size_t)row * RD + c * 4);
    atomicAdd(reinterpret_cast<float4*>(S + (size_t)atom * RD + c * 4), v);
}

// Y[8192, 128] = epilogue( preact(X[8192,K]) @ W[K,128] )
// epilogue: y = Z (+ bias) (* mul[row]) (+ add[row] * gv) (then ssp)
// Covers every op in a PhysNet module with one kernel.
__global__ void __launch_bounds__(NT, 1) gemm_fused(
    const float* __restrict__ X, int K,
    const float* __restrict__ W,
    const float* __restrict__ bias,   // [128] or null
    const float* __restrict__ mul,    // [N,128] or null  (elementwise *)
    const float* __restrict__ addp,   // [N,128] or null  (elementwise +, scaled by gv)
    const float* __restrict__ gv,     // [128] or null    (scales addp)
    float* __restrict__ Y,
    int preSSP, int postSSP)
{
    extern __shared__ float sm[];
    float* Xs = sm;            // [BM*K]   row-major
    float* Ws = sm + BM * K;   // [K*BN]   row-major

    const int tid = threadIdx.x;
    const size_t row0 = (size_t)blockIdx.x * BM;

    // X tile: rows are contiguous -> one linear float4 copy, ssp on the fly
    const float4* Xg = reinterpret_cast<const float4*>(X + row0 * K);
    const int nx4 = BM * K / 4;
    for (int i = tid; i < nx4; i += NT){
        float4 v = Xg[i];
        if (preSSP){ v.x = sspf(v.x); v.y = sspf(v.y); v.z = sspf(v.z); v.w = sspf(v.w); }
        reinterpret_cast<float4*>(Xs)[i] = v;
    }
    const int nw4 = K * BN / 4;
    const float4* Wg = reinterpret_cast<const float4*>(W);
    for (int i = tid; i < nw4; i += NT)
        reinterpret_cast<float4*>(Ws)[i] = Wg[i];
    __syncthreads();

    const int lane = tid & 31;
    const int warp = tid >> 5;
    const int m0 = warp * 16;     // 4 warps x 16 rows = 64 rows
    const int n0 = lane * 4;      // 32 lanes x 4 cols = 128 cols

    float acc[16][4];
    #pragma unroll
    for (int r = 0; r < 16; r++){ acc[r][0]=0.f; acc[r][1]=0.f; acc[r][2]=0.f; acc[r][3]=0.f; }

    const int K4 = K >> 2;
    #pragma unroll 4
    for (int k4 = 0; k4 < K4; k4++){
        const float* wr = Ws + (k4 * 4) * BN + n0;
        float4 b0 = *reinterpret_cast<const float4*>(wr);
        float4 b1 = *reinterpret_cast<const float4*>(wr + BN);
        float4 b2 = *reinterpret_cast<const float4*>(wr + 2 * BN);
        float4 b3 = *reinterpret_cast<const float4*>(wr + 3 * BN);
        const float* xr = Xs + m0 * K + k4 * 4;
        #pragma unroll
        for (int r = 0; r < 16; r++){
            float4 a = *reinterpret_cast<const float4*>(xr + r * K);  // warp-broadcast LDS
            acc[r][0] = fmaf(a.x, b0.x, acc[r][0]);
            acc[r][0] = fmaf(a.y, b1.x, acc[r][0]);
            acc[r][0] = fmaf(a.z, b2.x, acc[r][0]);
            acc[r][0] = fmaf(a.w, b3.x, acc[r][0]);
            acc[r][1] = fmaf(a.x, b0.y, acc[r][1]);
            acc[r][1] = fmaf(a.y, b1.y, acc[r][1]);
            acc[r][1] = fmaf(a.z, b2.y, acc[r][1]);
            acc[r][1] = fmaf(a.w, b3.y, acc[r][1]);
            acc[r][2] = fmaf(a.x, b0.z, acc[r][2]);
            acc[r][2] = fmaf(a.y, b1.z, acc[r][2]);
            acc[r][2] = fmaf(a.z, b2.z, acc[r][2]);
            acc[r][2] = fmaf(a.w, b3.z, acc[r][2]);
            acc[r][3] = fmaf(a.x, b0.w, acc[r][3]);
            acc[r][3] = fmaf(a.y, b1.w, acc[r][3]);
            acc[r][3] = fmaf(a.z, b2.w, acc[r][3]);
            acc[r][3] = fmaf(a.w, b3.w, acc[r][3]);
        }
    }

    float4 bv = make_float4(0.f, 0.f, 0.f, 0.f);
    if (bias) bv = *reinterpret_cast<const float4*>(bias + n0);
    float4 gvv = make_float4(1.f, 1.f, 1.f, 1.f);
    if (gv) gvv = *reinterpret_cast<const float4*>(gv + n0);

    #pragma unroll
    for (int r = 0; r < 16; r++){
        size_t o = (row0 + m0 + r) * BN + n0;
        float4 y = make_float4(acc[r][0] + bv.x, acc[r][1] + bv.y,
                               acc[r][2] + bv.z, acc[r][3] + bv.w);
        if (mul){
            float4 m = *reinterpret_cast<const float4*>(mul + o);
            y.x *= m.x; y.y *= m.y; y.z *= m.z; y.w *= m.w;
        }
        if (addp){
            float4 a = *reinterpret_cast<const float4*>(addp + o);
            y.x = fmaf(a.x, gvv.x, y.x);
            y.y = fmaf(a.y, gvv.y, y.y);
            y.z = fmaf(a.z, gvv.z, y.z);
            y.w = fmaf(a.w, gvv.w, y.w);
        }
        if (postSSP){ y.x = sspf(y.x); y.y = sspf(y.y); y.z = sspf(y.z); y.w = sspf(y.w); }
        *reinterpret_cast<float4*>(Y + o) = y;
    }
}

// E[row] (+)= ssp(Ybuf[row]) . W_out + b_out   (one warp per row)
__global__ void energy_kernel(const float* __restrict__ Ybuf,
                              const float* __restrict__ Wout,
                              const float* __restrict__ bout,
                              float* __restrict__ E, int init){
    int row  = blockIdx.x * 8 + (threadIdx.x >> 5);
    int lane = threadIdx.x & 31;
    float4 y = *reinterpret_cast<const float4*>(Ybuf + (size_t)row * FD + lane * 4);
    float4 w = *reinterpret_cast<const float4*>(Wout + lane * 4);
    float s = sspf(y.x)*w.x + sspf(y.y)*w.y + sspf(y.z)*w.z + sspf(y.w)*w.w;
    #pragma unroll
    for (int o = 16; o > 0; o >>= 1) s += __shfl_xor_sync(0xffffffff, s, o);
    if (lane == 0){
        float v = s + bout[0];
        E[row] = init ? v : (E[row] + v);
    }
}

extern "C" void kernel_launch(void* const* d_in, const int* in_sizes, int n_in,
                              void* d_out, int out_size)
{
    // metadata order (setup_inputs dict order)
    const float* features = (const float*)d_in[1];
    const float* radial   = (const float*)d_in[2];
    const int*   idx12    = (const int*)  d_in[3];
    const float* W_I   = (const float*)d_in[4];
    const float* b_I   = (const float*)d_in[5];
    const float* W_J   = (const float*)d_in[6];
    const float* b_J   = (const float*)d_in[7];
    const float* W_gate= (const float*)d_in[8];
    const float* gvec  = (const float*)d_in[9];
    const float* W_int = (const float*)d_in[10];
    const float* b_int = (const float*)d_in[11];
    const float* ri_W1 = (const float*)d_in[12];
    const float* ri_b1 = (const float*)d_in[13];
    const float* ri_W2 = (const float*)d_in[14];
    const float* ri_b2 = (const float*)d_in[15];
    const float* ra_W1 = (const float*)d_in[16];
    const float* ra_b1 = (const float*)d_in[17];
    const float* ra_W2 = (const float*)d_in[18];
    const float* ra_b2 = (const float*)d_in[19];
    const float* ro_W1 = (const float*)d_in[20];
    const float* ro_b1 = (const float*)d_in[21];
    const float* ro_W2 = (const float*)d_in[22];
    const float* ro_b2 = (const float*)d_in[23];
    const float* W_out = (const float*)d_in[24];
    const float* b_out = (const float*)d_in[25];

    const int P = in_sizes[3] / 2;            // 400000
    const int N = in_sizes[1] / FD;           // 8192
    const int L = in_sizes[4] / (FD * FD);    // 5
    const int nb = N / BM;                    // 128 blocks

    float *S, *bg, *bh, *bx, *bt, *fa, *fb;
    cudaGetSymbolAddress((void**)&S,  g_S);
    cudaGetSymbolAddress((void**)&bg, g_bg);
    cudaGetSymbolAddress((void**)&bh, g_bh);
    cudaGetSymbolAddress((void**)&bx, g_bx);
    cudaGetSymbolAddress((void**)&bt, g_bt);
    cudaGetSymbolAddress((void**)&fa, g_fa);
    cudaGetSymbolAddress((void**)&fb, g_fb);

    float* E = (float*)d_out;            // energies [N]
    float* outFeat = (float*)d_out + N;  // final feat [N, FD]

    const size_t smK128 = (size_t)(BM * FD + FD * BN) * sizeof(float);  // 96 KB
    const size_t smK64  = (size_t)(BM * RD + RD * BN) * sizeof(float);  // 48 KB
    cudaFuncSetAttribute(gemm_fused, cudaFuncAttributeMaxDynamicSharedMemorySize, (int)smK128);

    // --- once: S[i] = sum of radial rows over all (side,pair) occurrences of atom i
    zero_kernel<<<(N * RD + 255) / 256, 256>>>(S, N * RD);
    {
        int total = 2 * P * (RD / 4);
        scatter_kernel<<<(total + 255) / 256, 256>>>(radial, idx12, S, P);
    }

    const float* Fcur = features;
    for (int l = 0; l < L; l++){
        float* Fnxt = (l & 1) ? fb : fa;
        const float* wI = W_I + (size_t)l * FD * FD;  const float* bI = b_I + (size_t)l * FD;
        const float* wJ = W_J + (size_t)l * FD * FD;  const float* bJ = b_J + (size_t)l * FD;
        const float* wG = W_gate + (size_t)l * RD * FD;
        const float* gV = gvec  + (size_t)l * FD;
        const float* wN = W_int + (size_t)l * FD * FD; const float* bN = b_int + (size_t)l * FD;

        // g = ssp(ssp(F)@W_J + b_J) ; h_self = ssp(ssp(F)@W_I + b_I)
        gemm_fused<<<nb, NT, smK128>>>(Fcur, FD, wJ, bJ, nullptr, nullptr, nullptr, bg, 1, 1);
        gemm_fused<<<nb, NT, smK128>>>(Fcur, FD, wI, bI, nullptr, nullptr, nullptr, bh, 1, 1);
        // proto = (S @ W_gate) * g + h_self
        gemm_fused<<<nb, NT, smK64 >>>(S, RD, wG, nullptr, bg, bh, nullptr, bx, 0, 0);

        // interaction residual chain (3 blocks), in-place on bx
        for (int j = 0; j < 3; j++){
            const float* w1 = ri_W1 + (size_t)(l*3 + j) * FD * FD;
            const float* c1 = ri_b1 + (size_t)(l*3 + j) * FD;
            const float* w2 = ri_W2 + (size_t)(l*3 + j) * FD * FD;
            const float* c2 = ri_b2 + (size_t)(l*3 + j) * FD;
            gemm_fused<<<nb, NT, smK128>>>(bx, FD, w1, c1, nullptr, nullptr, nullptr, bt, 1, 0);
            gemm_fused<<<nb, NT, smK128>>>(bt, FD, w2, c2, nullptr, bx, nullptr, bx, 1, 0);
        }

        // feat2 = F*gvec + ssp(msg)@W_int + b_int
        gemm_fused<<<nb, NT, smK128>>>(bx, FD, wN, bN, nullptr, Fcur, gV, Fnxt, 1, 0);

        // atomic residual chain (2 blocks), in-place on Fnxt
        for (int j = 0; j < 2; j++){
            const float* w1 = ra_W1 + (size_t)(l*2 + j) * FD * FD;
            const float* c1 = ra_b1 + (size_t)(l*2 + j) * FD;
            const float* w2 = ra_W2 + (size_t)(l*2 + j) * FD * FD;
            const float* c2 = ra_b2 + (size_t)(l*2 + j) * FD;
            gemm_fused<<<nb, NT, smK128>>>(Fnxt, FD, w1, c1, nullptr, nullptr, nullptr, bt, 1, 0);
            gemm_fused<<<nb, NT, smK128>>>(bt,   FD, w2, c2, nullptr, Fnxt,  nullptr, Fnxt, 1, 0);
        }

        // output residual chain (1 block) -> bx (keeps Fnxt intact)
        {
            const float* w1 = ro_W1 + (size_t)l * FD * FD;
            const float* c1 = ro_b1 + (size_t)l * FD;
            const float* w2 = ro_W2 + (size_t)l * FD * FD;
            const float* c2 = ro_b2 + (size_t)l * FD;
            gemm_fused<<<nb, NT, smK128>>>(Fnxt, FD, w1, c1, nullptr, nullptr, nullptr, bt, 1, 0);
            gemm_fused<<<nb, NT, smK128>>>(bt,   FD, w2, c2, nullptr, Fnxt,  nullptr, bx, 1, 0);
        }

        // E (+)= ssp(bx) @ W_out + b_out
        energy_kernel<<<N / 8, 256>>>(bx, W_out + (size_t)l * FD, b_out + l, E, (l == 0) ? 1 : 0);

        Fcur = Fnxt;
    }

    // final features -> second output region
    if (out_size >= N + N * FD){
        cudaMemcpyAsync(outFeat, Fcur, (size_t)N * FD * sizeof(float),
                        cudaMemcpyDeviceToDevice);
    }
}

// round 7
// speedup vs baseline: 1.6714x; 1.6714x over previous
#include <cuda_runtime.h>
#include <cuda_bf16.h>
#include <stdint.h>
#include <math.h>

#define FD 128
#define RD 64
#define NMAX 8192
#define LMAX 5

// ---------------- scratch (no runtime allocation allowed) ----------------
__device__ float g_S [NMAX*RD];
__device__ float g_bg[NMAX*FD];
__device__ float g_bh[NMAX*FD];
__device__ float g_bx[NMAX*FD];
__device__ float g_bt[NMAX*FD];
__device__ float g_fa[NMAX*FD];
__device__ float g_fb[NMAX*FD];
// pre-transposed/split weight images: B[n][k] packed as uint32 (2 bf16 along k)
// 15 K=128 matrices per module (128*64 u32) + 1 K=64 gate (128*32 u32)
__device__ uint32_t g_Whi[LMAX*15*8192];
__device__ uint32_t g_Wlo[LMAX*15*8192];
__device__ uint32_t g_Ghi[LMAX*4096];
__device__ uint32_t g_Glo[LMAX*4096];

__device__ __forceinline__ uint32_t smem_u32(const void* p){
    uint32_t a;
    asm("{ .reg .u64 t; cvta.to.shared.u64 t, %1; cvt.u32.u64 %0, t; }" : "=r"(a) : "l"(p));
    return a;
}

__device__ __forceinline__ float sspf(float x){
    return fmaxf(x, 0.0f) + log1pf(__expf(-fabsf(x))) - 0.6931471805599453f;
}

__device__ __forceinline__ uint32_t bits2(__nv_bfloat162 v){
    return *reinterpret_cast<uint32_t*>(&v);
}

#define LDSM_X4(r0,r1,r2,r3,addr) \
    asm volatile("ldmatrix.sync.aligned.m8n8.x4.shared.b16 {%0,%1,%2,%3}, [%4];" \
        : "=r"(r0), "=r"(r1), "=r"(r2), "=r"(r3) : "r"(addr))

#define MMA16816(d, a0,a1,a2,a3, b0,b1) \
    asm volatile("mma.sync.aligned.m16n8k16.row.col.f32.bf16.bf16.f32 " \
        "{%0,%1,%2,%3}, {%4,%5,%6,%7}, {%8,%9}, {%0,%1,%2,%3};" \
        : "+f"((d)[0]), "+f"((d)[1]), "+f"((d)[2]), "+f"((d)[3]) \
        : "r"(a0), "r"(a1), "r"(a2), "r"(a3), "r"(b0), "r"(b1))

// ---------------- misc kernels ----------------
__global__ void zero_kernel(float* __restrict__ p, int n){
    int i = blockIdx.x * blockDim.x + threadIdx.x;
    if (i < n) p[i] = 0.0f;
}

// read each radial float4 chunk ONCE, scatter to both endpoints
__global__ void scatter_kernel(const float* __restrict__ radial,
                               const int*   __restrict__ idx,
                               float* __restrict__ S, int P){
    int gid = blockIdx.x * blockDim.x + threadIdx.x;
    if (gid >= P * (RD/4)) return;
    int c = gid & 15;
    int p = gid >> 4;
    float4 v = *reinterpret_cast<const float4*>(radial + (size_t)p * RD + c * 4);
    int a0 = idx[p];
    int a1 = idx[P + p];
    atomicAdd(reinterpret_cast<float4*>(S + (size_t)a0 * RD + c * 4), v);
    atomicAdd(reinterpret_cast<float4*>(S + (size_t)a1 * RD + c * 4), v);
}

// transpose + bf16 hi/lo split into global images. One block per matrix.
// Image layout: uint32 [128][K/2], entry (n, kk) packs {W[2kk][n], W[2kk+1][n]}.
__global__ void __launch_bounds__(256) prep_weights(
    const float* __restrict__ W_J, const float* __restrict__ W_I,
    const float* __restrict__ W_int,
    const float* __restrict__ ri_W1, const float* __restrict__ ri_W2,
    const float* __restrict__ ra_W1, const float* __restrict__ ra_W2,
    const float* __restrict__ ro_W1, const float* __restrict__ ro_W2,
    const float* __restrict__ W_gate, int L)
{
    int b = blockIdx.x;
    if (b < L * 15){
        int l = b / 15, slot = b % 15;
        const float* W;
        size_t ff = (size_t)FD * FD;
        if      (slot == 0)  W = W_J   + (size_t)l * ff;
        else if (slot == 1)  W = W_I   + (size_t)l * ff;
        else if (slot == 2)  W = W_int + (size_t)l * ff;
        else if (slot <= 5)  W = ri_W1 + (size_t)(l*3 + (slot-3))  * ff;
        else if (slot <= 8)  W = ri_W2 + (size_t)(l*3 + (slot-6))  * ff;
        else if (slot <= 10) W = ra_W1 + (size_t)(l*2 + (slot-9))  * ff;
        else if (slot <= 12) W = ra_W2 + (size_t)(l*2 + (slot-11)) * ff;
        else if (slot == 13) W = ro_W1 + (size_t)l * ff;
        else                 W = ro_W2 + (size_t)l * ff;
        uint32_t* oh = g_Whi + (size_t)b * 8192;
        uint32_t* ol = g_Wlo + (size_t)b * 8192;
        for (int i = threadIdx.x; i < 8192; i += 256){
            int n  = i >> 6;             // 0..127
            int kk = i & 63;             // 0..63  (k = 2*kk)
            float a = W[(size_t)(2*kk)   * FD + n];
            float c = W[(size_t)(2*kk+1) * FD + n];
            __nv_bfloat162 h2 = __floats2bfloat162_rn(a, c);
            __nv_bfloat162 l2 = __floats2bfloat162_rn(a - __bfloat162float(h2.x),
                                                      c - __bfloat162float(h2.y));
            oh[i] = bits2(h2);
            ol[i] = bits2(l2);
        }
    } else {
        int l = b - L * 15;
        const float* W = W_gate + (size_t)l * RD * FD;   // [64, 128]
        uint32_t* oh = g_Ghi + (size_t)l * 4096;
        uint32_t* ol = g_Glo + (size_t)l * 4096;
        for (int i = threadIdx.x; i < 4096; i += 256){
            int n  = i >> 5;             // 0..127
            int kk = i & 31;             // 0..31
            float a = W[(size_t)(2*kk)   * FD + n];
            float c = W[(size_t)(2*kk+1) * FD + n];
            __nv_bfloat162 h2 = __floats2bfloat162_rn(a, c);
            __nv_bfloat162 l2 = __floats2bfloat162_rn(a - __bfloat162float(h2.x),
                                                      c - __bfloat162float(h2.y));
            oh[i] = bits2(h2);
            ol[i] = bits2(l2);
        }
    }
}

// ---------------- tensor-core GEMM via mma.sync (HMMA), bf16x3 split ----------------
// Y[8192,128] = epilogue( preact(X[8192,K]) @ W[K,128] )
// Tile: BM=64 x BN=128, 256 threads, warps 2(m) x 4(n), warp tile 32x32.
// Smem planes padded to row stride (K+8)*2 bytes -> conflict-free ldmatrix.
template<int K>
__global__ void __launch_bounds__(256, 1) gemm_tc(
    const float* __restrict__ X,
    const uint32_t* __restrict__ Bhi_img, const uint32_t* __restrict__ Blo_img,
    const float* __restrict__ bias, const float* __restrict__ mul,
    const float* __restrict__ addp, const float* __restrict__ gv,
    float* __restrict__ Y, int preSSP, int postSSP)
{
    extern __shared__ char smem[];
    const int tid = threadIdx.x, wid = tid >> 5, lane = tid & 31;
    constexpr int SA = (K + 8) * 2;          // bytes per smem row
    char* Ah = smem;
    char* Al = smem + 64 * SA;
    char* Bh = smem + 128 * SA;
    char* Bl = smem + 256 * SA;

    // B planes: straight copy of pre-split images into padded rows
    {
        constexpr int CH = K >> 3;           // 16B chunks per row
        const uint4* bh4 = reinterpret_cast<const uint4*>(Bhi_img);
        const uint4* bl4 = reinterpret_cast<const uint4*>(Blo_img);
        #pragma unroll 4
        for (int i = tid; i < 128 * CH; i += 256){
            int n = i / CH, c = i - n * CH;
            *reinterpret_cast<uint4*>(Bh + n * SA + c * 16) = bh4[i];
            *reinterpret_cast<uint4*>(Bl + n * SA + c * 16) = bl4[i];
        }
    }
    // A planes: fp32 load, optional ssp, hi/lo bf16 split
    {
        const float* Xr = X + (size_t)blockIdx.x * 64 * K;
        constexpr int HF = K >> 1;
        #pragma unroll 4
        for (int i = tid; i < 64 * HF; i += 256){
            int row = i / HF, k2 = i - row * HF;
            float2 v = *reinterpret_cast<const float2*>(Xr + (size_t)row * K + 2 * k2);
            if (preSSP){ v.x = sspf(v.x); v.y = sspf(v.y); }
            __nv_bfloat162 h2 = __floats2bfloat162_rn(v.x, v.y);
            __nv_bfloat162 l2 = __floats2bfloat162_rn(v.x - __bfloat162float(h2.x),
                                                      v.y - __bfloat162float(h2.y));
            *reinterpret_cast<uint32_t*>(Ah + row * SA + k2 * 4) = bits2(h2);
            *reinterpret_cast<uint32_t*>(Al + row * SA + k2 * 4) = bits2(l2);
        }
    }
    __syncthreads();

    const int wm = wid >> 2;                 // 0..1  (32 rows each)
    const int wn = wid & 3;                  // 0..3  (32 cols each)
    const int mat = lane >> 3, r = lane & 7;

    // ldmatrix lane base offsets (relative to plane base), advance by k0*2 bytes
    // A x4 mats: (m-lo,k-lo),(m-hi,k-lo),(m-lo,k-hi),(m-hi,k-hi)
    uint32_t aoff[2], boff[2];
    #pragma unroll
    for (int mt = 0; mt < 2; mt++)
        aoff[mt] = (uint32_t)((wm*32 + mt*16 + r + ((mat & 1) << 3)) * SA
                              + ((mat >> 1) << 3) * 2);
    // B x4 mats: (n-lo,k-lo),(n-lo,k-hi),(n-hi,k-lo),(n-hi,k-hi)
    #pragma unroll
    for (int np = 0; np < 2; np++)
        boff[np] = (uint32_t)((wn*32 + np*16 + r + ((mat >> 1) << 3)) * SA
                              + ((mat & 1) << 3) * 2);

    const uint32_t sAh = smem_u32(Ah), sAl = smem_u32(Al);
    const uint32_t sBh = smem_u32(Bh), sBl = smem_u32(Bl);

    float acc[2][4][4];
    #pragma unroll
    for (int i = 0; i < 2; i++)
        #pragma unroll
        for (int j = 0; j < 4; j++)
            #pragma unroll
            for (int q = 0; q < 4; q++) acc[i][j][q] = 0.f;

    #pragma unroll
    for (int pass = 0; pass < 3; pass++){
        const uint32_t pa = (pass == 2) ? sAl : sAh;
        const uint32_t pb = (pass == 1) ? sBl : sBh;
        #pragma unroll
        for (int k0 = 0; k0 < K; k0 += 16){
            uint32_t a[2][4], b[2][4];
            #pragma unroll
            for (int mt = 0; mt < 2; mt++)
                LDSM_X4(a[mt][0], a[mt][1], a[mt][2], a[mt][3], pa + aoff[mt] + k0*2);
            #pragma unroll
            for (int np = 0; np < 2; np++)
                LDSM_X4(b[np][0], b[np][1], b[np][2], b[np][3], pb + boff[np] + k0*2);
            #pragma unroll
            for (int mt = 0; mt < 2; mt++)
                #pragma unroll
                for (int nt = 0; nt < 4; nt++)
                    MMA16816(acc[mt][nt],
                             a[mt][0], a[mt][1], a[mt][2], a[mt][3],
                             b[nt>>1][(nt&1)*2], b[nt>>1][(nt&1)*2+1]);
        }
    }

    // epilogue: lane holds rows (g, g+8), cols (c, c+1) per tile
    const int g = lane >> 2, c2 = (lane & 3) * 2;
    const int row0 = blockIdx.x * 64 + wm * 32;
    #pragma unroll
    for (int mt = 0; mt < 2; mt++){
        #pragma unroll
        for (int nt = 0; nt < 4; nt++){
            int col = wn * 32 + nt * 8 + c2;
            float2 bv = make_float2(0.f, 0.f);
            if (bias) bv = *reinterpret_cast<const float2*>(bias + col);
            float2 gvv = make_float2(1.f, 1.f);
            if (gv) gvv = *reinterpret_cast<const float2*>(gv + col);
            #pragma unroll
            for (int h = 0; h < 2; h++){
                int row = row0 + mt * 16 + g + h * 8;
                size_t o = (size_t)row * FD + col;
                float2 y = make_float2(acc[mt][nt][h*2] + bv.x,
                                       acc[mt][nt][h*2+1] + bv.y);
                if (mul){
                    float2 m = *reinterpret_cast<const float2*>(mul + o);
                    y.x *= m.x; y.y *= m.y;
                }
                if (addp){
                    float2 a = *reinterpret_cast<const float2*>(addp + o);
                    y.x = fmaf(a.x, gvv.x, y.x);
                    y.y = fmaf(a.y, gvv.y, y.y);
                }
                if (postSSP){ y.x = sspf(y.x); y.y = sspf(y.y); }
                *reinterpret_cast<float2*>(Y + o) = y;
            }
        }
    }
}

// E[row] (+)= ssp(Ybuf[row]) . W_out + b_out   (one warp per row)
__global__ void energy_kernel(const float* __restrict__ Ybuf,
                              const float* __restrict__ Wout,
                              const float* __restrict__ bout,
                              float* __restrict__ E, int init){
    int row  = blockIdx.x * 8 + (threadIdx.x >> 5);
    int lane = threadIdx.x & 31;
    float4 y = *reinterpret_cast<const float4*>(Ybuf + (size_t)row * FD + lane * 4);
    float4 w = *reinterpret_cast<const float4*>(Wout + lane * 4);
    float s = sspf(y.x)*w.x + sspf(y.y)*w.y + sspf(y.z)*w.z + sspf(y.w)*w.w;
    #pragma unroll
    for (int o = 16; o > 0; o >>= 1) s += __shfl_xor_sync(0xffffffff, s, o);
    if (lane == 0){
        float v = s + bout[0];
        E[row] = init ? v : (E[row] + v);
    }
}

// ---------------- launch ----------------
extern "C" void kernel_launch(void* const* d_in, const int* in_sizes, int n_in,
                              void* d_out, int out_size)
{
    const float* features = (const float*)d_in[1];
    const float* radial   = (const float*)d_in[2];
    const int*   idx12    = (const int*)  d_in[3];
    const float* W_I   = (const float*)d_in[4];
    const float* b_I   = (const float*)d_in[5];
    const float* W_J   = (const float*)d_in[6];
    const float* b_J   = (const float*)d_in[7];
    const float* W_gate= (const float*)d_in[8];
    const float* gvec  = (const float*)d_in[9];
    const float* W_int = (const float*)d_in[10];
    const float* b_int = (const float*)d_in[11];
    const float* ri_b1 = (const float*)d_in[13];
    const float* ri_b2 = (const float*)d_in[15];
    const float* ra_b1 = (const float*)d_in[17];
    const float* ra_b2 = (const float*)d_in[19];
    const float* ro_b1 = (const float*)d_in[21];
    const float* ro_b2 = (const float*)d_in[23];
    const float* W_out = (const float*)d_in[24];
    const float* b_out = (const float*)d_in[25];

    const int P = in_sizes[3] / 2;
    const int N = in_sizes[1] / FD;
    const int L = in_sizes[4] / (FD * FD);
    const int nb = N / 64;                   // 128 CTAs

    float *S, *bg, *bh, *bx, *bt, *fa, *fb;
    cudaGetSymbolAddress((void**)&S,  g_S);
    cudaGetSymbolAddress((void**)&bg, g_bg);
    cudaGetSymbolAddress((void**)&bh, g_bh);
    cudaGetSymbolAddress((void**)&bx, g_bx);
    cudaGetSymbolAddress((void**)&bt, g_bt);
    cudaGetSymbolAddress((void**)&fa, g_fa);
    cudaGetSymbolAddress((void**)&fb, g_fb);
    uint32_t *Whi, *Wlo, *Ghi, *Glo;
    cudaGetSymbolAddress((void**)&Whi, g_Whi);
    cudaGetSymbolAddress((void**)&Wlo, g_Wlo);
    cudaGetSymbolAddress((void**)&Ghi, g_Ghi);
    cudaGetSymbolAddress((void**)&Glo, g_Glo);

    float* E = (float*)d_out;
    float* outFeat = (float*)d_out + N;

    const int sm128 = 384 * (128 + 8) * 2;   // 104448 B
    const int sm64  = 384 * (64 + 8) * 2;    //  55296 B
    cudaFuncSetAttribute(gemm_tc<128>, cudaFuncAttributeMaxDynamicSharedMemorySize, sm128);
    cudaFuncSetAttribute(gemm_tc<64>,  cudaFuncAttributeMaxDynamicSharedMemorySize, sm64);

    // one-time per launch: weight images + pair aggregation
    prep_weights<<<L * 15 + L, 256>>>(W_J, W_I, W_int,
        (const float*)d_in[12], (const float*)d_in[14],
        (const float*)d_in[16], (const float*)d_in[18],
        (const float*)d_in[20], (const float*)d_in[22], W_gate, L);
    zero_kernel<<<(N * RD + 255) / 256, 256>>>(S, N * RD);
    scatter_kernel<<<(P * (RD/4) + 255) / 256, 256>>>(radial, idx12, S, P);

    const float* Fcur = features;
    for (int l = 0; l < L; l++){
        float* Fnxt = (l & 1) ? fb : fa;
        const uint32_t* mh = Whi + (size_t)(l * 15) * 8192;
        const uint32_t* ml = Wlo + (size_t)(l * 15) * 8192;
        const float* bJ = b_J + (size_t)l * FD;
        const float* bI = b_I + (size_t)l * FD;
        const float* bN = b_int + (size_t)l * FD;
        const float* gV = gvec + (size_t)l * FD;

        // g = ssp(ssp(F)@W_J + b_J) ; h_self = ssp(ssp(F)@W_I + b_I)
        gemm_tc<128><<<nb, 256, sm128>>>(Fcur, mh + 0*8192, ml + 0*8192, bJ,
                                         nullptr, nullptr, nullptr, bg, 1, 1);
        gemm_tc<128><<<nb, 256, sm128>>>(Fcur, mh + 1*8192, ml + 1*8192, bI,
                                         nullptr, nullptr, nullptr, bh, 1, 1);
        // proto = (S @ W_gate) * g + h_self
        gemm_tc<64><<<nb, 256, sm64>>>(S, Ghi + (size_t)l*4096, Glo + (size_t)l*4096,
                                       nullptr, bg, bh, nullptr, bx, 0, 0);

        // interaction residual chain (3 blocks)
        for (int j = 0; j < 3; j++){
            const float* c1 = ri_b1 + (size_t)(l*3 + j) * FD;
            const float* c2 = ri_b2 + (size_t)(l*3 + j) * FD;
            gemm_tc<128><<<nb, 256, sm128>>>(bx, mh + (3+j)*8192, ml + (3+j)*8192, c1,
                                             nullptr, nullptr, nullptr, bt, 1, 0);
            gemm_tc<128><<<nb, 256, sm128>>>(bt, mh + (6+j)*8192, ml + (6+j)*8192, c2,
                                             nullptr, bx, nullptr, bx, 1, 0);
        }
        // feat2 = F*gvec + ssp(msg)@W_int + b_int
        gemm_tc<128><<<nb, 256, sm128>>>(bx, mh + 2*8192, ml + 2*8192, bN,
                                         nullptr, Fcur, gV, Fnxt, 1, 0);
        // atomic residual chain (2 blocks)
        for (int j = 0; j < 2; j++){
            const float* c1 = ra_b1 + (size_t)(l*2 + j) * FD;
            const float* c2 = ra_b2 + (size_t)(l*2 + j) * FD;
            gemm_tc<128><<<nb, 256, sm128>>>(Fnxt, mh + (9+j)*8192,  ml + (9+j)*8192,  c1,
                                             nullptr, nullptr, nullptr, bt, 1, 0);
            gemm_tc<128><<<nb, 256, sm128>>>(bt,   mh + (11+j)*8192, ml + (11+j)*8192, c2,
                                             nullptr, Fnxt, nullptr, Fnxt, 1, 0);
        }
        // output residual chain (1 block) -> bx
        {
            const float* c1 = ro_b1 + (size_t)l * FD;
            const float* c2 = ro_b2 + (size_t)l * FD;
            gemm_tc<128><<<nb, 256, sm128>>>(Fnxt, mh + 13*8192, ml + 13*8192, c1,
                                             nullptr, nullptr, nullptr, bt, 1, 0);
            gemm_tc<128><<<nb, 256, sm128>>>(bt,   mh + 14*8192, ml + 14*8192, c2,
                                             nullptr, Fnxt, nullptr, bx, 1, 0);
        }
        // E (+)= ssp(bx) @ W_out + b_out
        energy_kernel<<<N / 8, 256>>>(bx, W_out + (size_t)l * FD, b_out + l, E, (l == 0) ? 1 : 0);

        Fcur = Fnxt;
    }

    if (out_size >= N + N * FD){
        cudaMemcpyAsync(outFeat, Fcur, (size_t)N * FD * sizeof(float),
                        cudaMemcpyDeviceToDevice);
    }
}

// round 8
// speedup vs baseline: 1.7265x; 1.0329x over previous
#include <cuda_runtime.h>
#include <cuda_bf16.h>
#include <stdint.h>
#include <math.h>

#define FD 128
#define RD 64
#define NMAX 8192
#define LMAX 5

// ---------------- scratch (no runtime allocation allowed) ----------------
__device__ float g_S [NMAX*RD];
__device__ float g_bg[NMAX*FD];
__device__ float g_bh[NMAX*FD];
__device__ float g_bx[NMAX*FD];
__device__ float g_bt[NMAX*FD];
__device__ float g_fa[NMAX*FD];
__device__ float g_fb[NMAX*FD];
// pre-transposed/split weight images: B[n][k] packed as uint32 (2 bf16 along k)
__device__ uint32_t g_Whi[LMAX*15*8192];
__device__ uint32_t g_Wlo[LMAX*15*8192];
__device__ uint32_t g_Ghi[LMAX*4096];
__device__ uint32_t g_Glo[LMAX*4096];

__device__ __forceinline__ uint32_t smem_u32(const void* p){
    uint32_t a;
    asm("{ .reg .u64 t; cvta.to.shared.u64 t, %1; cvt.u32.u64 %0, t; }" : "=r"(a) : "l"(p));
    return a;
}

__device__ __forceinline__ float sspf(float x){
    return fmaxf(x, 0.0f) + log1pf(__expf(-fabsf(x))) - 0.6931471805599453f;
}

__device__ __forceinline__ uint32_t bits2(__nv_bfloat162 v){
    return *reinterpret_cast<uint32_t*>(&v);
}

#define LDSM_X4(r0,r1,r2,r3,addr) \
    asm volatile("ldmatrix.sync.aligned.m8n8.x4.shared.b16 {%0,%1,%2,%3}, [%4];" \
        : "=r"(r0), "=r"(r1), "=r"(r2), "=r"(r3) : "r"(addr))

#define MMA16816(d, a0,a1,a2,a3, b0,b1) \
    asm volatile("mma.sync.aligned.m16n8k16.row.col.f32.bf16.bf16.f32 " \
        "{%0,%1,%2,%3}, {%4,%5,%6,%7}, {%8,%9}, {%0,%1,%2,%3};" \
        : "+f"((d)[0]), "+f"((d)[1]), "+f"((d)[2]), "+f"((d)[3]) \
        : "r"(a0), "r"(a1), "r"(a2), "r"(a3), "r"(b0), "r"(b1))

#define CP_ASYNC16(saddr, gptr) \
    asm volatile("cp.async.cg.shared.global [%0], [%1], 16;" :: "r"(saddr), "l"(gptr))
#define CP_COMMIT() asm volatile("cp.async.commit_group;" ::: "memory")
#define CP_WAIT0()  asm volatile("cp.async.wait_group 0;" ::: "memory")

// ---------------- misc kernels ----------------
__global__ void zero_kernel(float* __restrict__ p, int n){
    int i = blockIdx.x * blockDim.x + threadIdx.x;
    if (i < n) p[i] = 0.0f;
}

// read each radial float4 chunk ONCE, scatter to both endpoints
__global__ void scatter_kernel(const float* __restrict__ radial,
                               const int*   __restrict__ idx,
                               float* __restrict__ S, int P){
    int gid = blockIdx.x * blockDim.x + threadIdx.x;
    if (gid >= P * (RD/4)) return;
    int c = gid & 15;
    int p = gid >> 4;
    float4 v = *reinterpret_cast<const float4*>(radial + (size_t)p * RD + c * 4);
    int a0 = idx[p];
    int a1 = idx[P + p];
    atomicAdd(reinterpret_cast<float4*>(S + (size_t)a0 * RD + c * 4), v);
    atomicAdd(reinterpret_cast<float4*>(S + (size_t)a1 * RD + c * 4), v);
}

// transpose + bf16 hi/lo split into global images. One block per matrix.
__global__ void __launch_bounds__(256) prep_weights(
    const float* __restrict__ W_J, const float* __restrict__ W_I,
    const float* __restrict__ W_int,
    const float* __restrict__ ri_W1, const float* __restrict__ ri_W2,
    const float* __restrict__ ra_W1, const float* __restrict__ ra_W2,
    const float* __restrict__ ro_W1, const float* __restrict__ ro_W2,
    const float* __restrict__ W_gate, int L)
{
    int b = blockIdx.x;
    if (b < L * 15){
        int l = b / 15, slot = b % 15;
        const float* W;
        size_t ff = (size_t)FD * FD;
        if      (slot == 0)  W = W_J   + (size_t)l * ff;
        else if (slot == 1)  W = W_I   + (size_t)l * ff;
        else if (slot == 2)  W = W_int + (size_t)l * ff;
        else if (slot <= 5)  W = ri_W1 + (size_t)(l*3 + (slot-3))  * ff;
        else if (slot <= 8)  W = ri_W2 + (size_t)(l*3 + (slot-6))  * ff;
        else if (slot <= 10) W = ra_W1 + (size_t)(l*2 + (slot-9))  * ff;
        else if (slot <= 12) W = ra_W2 + (size_t)(l*2 + (slot-11)) * ff;
        else if (slot == 13) W = ro_W1 + (size_t)l * ff;
        else                 W = ro_W2 + (size_t)l * ff;
        uint32_t* oh = g_Whi + (size_t)b * 8192;
        uint32_t* ol = g_Wlo + (size_t)b * 8192;
        for (int i = threadIdx.x; i < 8192; i += 256){
            int n  = i >> 6;
            int kk = i & 63;
            float a = W[(size_t)(2*kk)   * FD + n];
            float c = W[(size_t)(2*kk+1) * FD + n];
            __nv_bfloat162 h2 = __floats2bfloat162_rn(a, c);
            __nv_bfloat162 l2 = __floats2bfloat162_rn(a - __bfloat162float(h2.x),
                                                      c - __bfloat162float(h2.y));
            oh[i] = bits2(h2);
            ol[i] = bits2(l2);
        }
    } else {
        int l = b - L * 15;
        const float* W = W_gate + (size_t)l * RD * FD;   // [64, 128]
        uint32_t* oh = g_Ghi + (size_t)l * 4096;
        uint32_t* ol = g_Glo + (size_t)l * 4096;
        for (int i = threadIdx.x; i < 4096; i += 256){
            int n  = i >> 5;
            int kk = i & 31;
            float a = W[(size_t)(2*kk)   * FD + n];
            float c = W[(size_t)(2*kk+1) * FD + n];
            __nv_bfloat162 h2 = __floats2bfloat162_rn(a, c);
            __nv_bfloat162 l2 = __floats2bfloat162_rn(a - __bfloat162float(h2.x),
                                                      c - __bfloat162float(h2.y));
            oh[i] = bits2(h2);
            ol[i] = bits2(l2);
        }
    }
}

// ---------------- tensor-core GEMM via mma.sync (HMMA), bf16x3 split ----------------
// Y[8192,128] = epilogue( preact(X[8192,K]) @ W[K,128] )
// Tile: BM=64 x BN=128, 512 threads, warps 2(m) x 8(n), warp tile 32x16.
// Single k-loop: all 3 split products accumulate into one fp32 acc.
template<int K>
__global__ void __launch_bounds__(512, 1) gemm_tc(
    const float* __restrict__ X,
    const uint32_t* __restrict__ Bhi_img, const uint32_t* __restrict__ Blo_img,
    const float* __restrict__ bias, const float* __restrict__ mul,
    const float* __restrict__ addp, const float* __restrict__ gv,
    float* __restrict__ Y, int preSSP, int postSSP)
{
    extern __shared__ char smem[];
    const int tid = threadIdx.x, wid = tid >> 5, lane = tid & 31;
    constexpr int SA = (K + 8) * 2;          // bytes per smem row (17/9 x 16B banks)
    char* Ah = smem;
    char* Al = smem + 64 * SA;
    char* Bh = smem + 128 * SA;
    char* Bl = smem + 256 * SA;
    const uint32_t sAh = smem_u32(Ah), sAl = smem_u32(Al);
    const uint32_t sBh = smem_u32(Bh), sBl = smem_u32(Bl);

    // B planes via cp.async (fly under the A transform)
    {
        constexpr int CH = K >> 3;           // 16B chunks per row
        const uint4* bh4 = reinterpret_cast<const uint4*>(Bhi_img);
        const uint4* bl4 = reinterpret_cast<const uint4*>(Blo_img);
        #pragma unroll
        for (int i = tid; i < 128 * CH; i += 512){
            int n = i / CH, c = i - n * CH;
            uint32_t d = (uint32_t)(n * SA + c * 16);
            CP_ASYNC16(sBh + d, bh4 + i);
            CP_ASYNC16(sBl + d, bl4 + i);
        }
        CP_COMMIT();
    }
    // A planes: fp32 load, optional ssp, hi/lo bf16 split
    {
        const float* Xr = X + (size_t)blockIdx.x * 64 * K;
        constexpr int HF = K >> 1;
        #pragma unroll
        for (int i = tid; i < 64 * HF; i += 512){
            int row = i / HF, k2 = i - row * HF;
            float2 v = *reinterpret_cast<const float2*>(Xr + (size_t)row * K + 2 * k2);
            if (preSSP){ v.x = sspf(v.x); v.y = sspf(v.y); }
            __nv_bfloat162 h2 = __floats2bfloat162_rn(v.x, v.y);
            __nv_bfloat162 l2 = __floats2bfloat162_rn(v.x - __bfloat162float(h2.x),
                                                      v.y - __bfloat162float(h2.y));
            *reinterpret_cast<uint32_t*>(Ah + row * SA + k2 * 4) = bits2(h2);
            *reinterpret_cast<uint32_t*>(Al + row * SA + k2 * 4) = bits2(l2);
        }
    }
    CP_WAIT0();
    __syncthreads();

    const int wm = wid >> 3;                 // 0..1  (32 rows each)
    const int wn = wid & 7;                  // 0..7  (16 cols each)
    const int mat = lane >> 3, r = lane & 7;

    // A x4 mats: (m-lo,k-lo),(m-hi,k-lo),(m-lo,k-hi),(m-hi,k-hi)
    uint32_t aoff[2];
    #pragma unroll
    for (int mt = 0; mt < 2; mt++)
        aoff[mt] = (uint32_t)((wm*32 + mt*16 + r + ((mat & 1) << 3)) * SA
                              + ((mat >> 1) << 3) * 2);
    // B x4 mats: (n-lo,k-lo),(n-lo,k-hi),(n-hi,k-lo),(n-hi,k-hi)
    const uint32_t boff = (uint32_t)((wn*16 + ((mat >> 1) << 3) + r) * SA
                                     + ((mat & 1) << 3) * 2);

    float acc[2][2][4];
    #pragma unroll
    for (int i = 0; i < 2; i++)
        #pragma unroll
        for (int j = 0; j < 2; j++)
            #pragma unroll
            for (int q = 0; q < 4; q++) acc[i][j][q] = 0.f;

    #pragma unroll
    for (int k0 = 0; k0 < K; k0 += 16){
        uint32_t ah[2][4], al[2][4], bh[4], bl[4];
        #pragma unroll
        for (int mt = 0; mt < 2; mt++){
            LDSM_X4(ah[mt][0], ah[mt][1], ah[mt][2], ah[mt][3], sAh + aoff[mt] + k0*2);
            LDSM_X4(al[mt][0], al[mt][1], al[mt][2], al[mt][3], sAl + aoff[mt] + k0*2);
        }
        LDSM_X4(bh[0], bh[1], bh[2], bh[3], sBh + boff + k0*2);
        LDSM_X4(bl[0], bl[1], bl[2], bl[3], sBl + boff + k0*2);
        #pragma unroll
        for (int mt = 0; mt < 2; mt++)
            #pragma unroll
            for (int nt = 0; nt < 2; nt++){
                MMA16816(acc[mt][nt], ah[mt][0], ah[mt][1], ah[mt][2], ah[mt][3],
                         bh[nt*2], bh[nt*2+1]);
                MMA16816(acc[mt][nt], ah[mt][0], ah[mt][1], ah[mt][2], ah[mt][3],
                         bl[nt*2], bl[nt*2+1]);
                MMA16816(acc[mt][nt], al[mt][0], al[mt][1], al[mt][2], al[mt][3],
                         bh[nt*2], bh[nt*2+1]);
            }
    }

    // epilogue: lane holds rows (g, g+8), cols (c2, c2+1) per 16x8 tile
    const int g = lane >> 2, c2 = (lane & 3) * 2;
    const int row0 = blockIdx.x * 64 + wm * 32;
    #pragma unroll
    for (int mt = 0; mt < 2; mt++){
        #pragma unroll
        for (int nt = 0; nt < 2; nt++){
            int col = wn * 16 + nt * 8 + c2;
            float2 bv = make_float2(0.f, 0.f);
            if (bias) bv = *reinterpret_cast<const float2*>(bias + col);
            float2 gvv = make_float2(1.f, 1.f);
            if (gv) gvv = *reinterpret_cast<const float2*>(gv + col);
            #pragma unroll
            for (int h = 0; h < 2; h++){
                int row = row0 + mt * 16 + g + h * 8;
                size_t o = (size_t)row * FD + col;
                float2 y = make_float2(acc[mt][nt][h*2] + bv.x,
                                       acc[mt][nt][h*2+1] + bv.y);
                if (mul){
                    float2 m = *reinterpret_cast<const float2*>(mul + o);
                    y.x *= m.x; y.y *= m.y;
                }
                if (addp){
                    float2 a = *reinterpret_cast<const float2*>(addp + o);
                    y.x = fmaf(a.x, gvv.x, y.x);
                    y.y = fmaf(a.y, gvv.y, y.y);
                }
                if (postSSP){ y.x = sspf(y.x); y.y = sspf(y.y); }
                *reinterpret_cast<float2*>(Y + o) = y;
            }
        }
    }
}

// E[row] (+)= ssp(Ybuf[row]) . W_out + b_out   (one warp per row)
__global__ void energy_kernel(const float* __restrict__ Ybuf,
                              const float* __restrict__ Wout,
                              const float* __restrict__ bout,
                              float* __restrict__ E, int init){
    int row  = blockIdx.x * 8 + (threadIdx.x >> 5);
    int lane = threadIdx.x & 31;
    float4 y = *reinterpret_cast<const float4*>(Ybuf + (size_t)row * FD + lane * 4);
    float4 w = *reinterpret_cast<const float4*>(Wout + lane * 4);
    float s = sspf(y.x)*w.x + sspf(y.y)*w.y + sspf(y.z)*w.z + sspf(y.w)*w.w;
    #pragma unroll
    for (int o = 16; o > 0; o >>= 1) s += __shfl_xor_sync(0xffffffff, s, o);
    if (lane == 0){
        float v = s + bout[0];
        E[row] = init ? v : (E[row] + v);
    }
}

// ---------------- launch ----------------
extern "C" void kernel_launch(void* const* d_in, const int* in_sizes, int n_in,
                              void* d_out, int out_size)
{
    const float* features = (const float*)d_in[1];
    const float* radial   = (const float*)d_in[2];
    const int*   idx12    = (const int*)  d_in[3];
    const float* W_I   = (const float*)d_in[4];
    const float* b_I   = (const float*)d_in[5];
    const float* W_J   = (const float*)d_in[6];
    const float* b_J   = (const float*)d_in[7];
    const float* W_gate= (const float*)d_in[8];
    const float* gvec  = (const float*)d_in[9];
    const float* W_int = (const float*)d_in[10];
    const float* b_int = (const float*)d_in[11];
    const float* ri_b1 = (const float*)d_in[13];
    const float* ri_b2 = (const float*)d_in[15];
    const float* ra_b1 = (const float*)d_in[17];
    const float* ra_b2 = (const float*)d_in[19];
    const float* ro_b1 = (const float*)d_in[21];
    const float* ro_b2 = (const float*)d_in[23];
    const float* W_out = (const float*)d_in[24];
    const float* b_out = (const float*)d_in[25];

    const int P = in_sizes[3] / 2;
    const int N = in_sizes[1] / FD;
    const int L = in_sizes[4] / (FD * FD);
    const int nb = N / 64;                   // 128 CTAs

    float *S, *bg, *bh, *bx, *bt, *fa, *fb;
    cudaGetSymbolAddress((void**)&S,  g_S);
    cudaGetSymbolAddress((void**)&bg, g_bg);
    cudaGetSymbolAddress((void**)&bh, g_bh);
    cudaGetSymbolAddress((void**)&bx, g_bx);
    cudaGetSymbolAddress((void**)&bt, g_bt);
    cudaGetSymbolAddress((void**)&fa, g_fa);
    cudaGetSymbolAddress((void**)&fb, g_fb);
    uint32_t *Whi, *Wlo, *Ghi, *Glo;
    cudaGetSymbolAddress((void**)&Whi, g_Whi);
    cudaGetSymbolAddress((void**)&Wlo, g_Wlo);
    cudaGetSymbolAddress((void**)&Ghi, g_Ghi);
    cudaGetSymbolAddress((void**)&Glo, g_Glo);

    float* E = (float*)d_out;
    float* outFeat = (float*)d_out + N;

    const int sm128 = 384 * (128 + 8) * 2;   // 104448 B
    const int sm64  = 384 * (64 + 8) * 2;    //  55296 B
    cudaFuncSetAttribute(gemm_tc<128>, cudaFuncAttributeMaxDynamicSharedMemorySize, sm128);
    cudaFuncSetAttribute(gemm_tc<64>,  cudaFuncAttributeMaxDynamicSharedMemorySize, sm64);

    // one-time per launch: weight images + pair aggregation
    prep_weights<<<L * 15 + L, 256>>>(W_J, W_I, W_int,
        (const float*)d_in[12], (const float*)d_in[14],
        (const float*)d_in[16], (const float*)d_in[18],
        (const float*)d_in[20], (const float*)d_in[22], W_gate, L);
    zero_kernel<<<(N * RD + 255) / 256, 256>>>(S, N * RD);
    scatter_kernel<<<(P * (RD/4) + 255) / 256, 256>>>(radial, idx12, S, P);

    const float* Fcur = features;
    for (int l = 0; l < L; l++){
        float* Fnxt = (l & 1) ? fb : fa;
        const uint32_t* mh = Whi + (size_t)(l * 15) * 8192;
        const uint32_t* ml = Wlo + (size_t)(l * 15) * 8192;
        const float* bJ = b_J + (size_t)l * FD;
        const float* bI = b_I + (size_t)l * FD;
        const float* bN = b_int + (size_t)l * FD;
        const float* gV = gvec + (size_t)l * FD;

        // g = ssp(ssp(F)@W_J + b_J) ; h_self = ssp(ssp(F)@W_I + b_I)
        gemm_tc<128><<<nb, 512, sm128>>>(Fcur, mh + 0*8192, ml + 0*8192, bJ,
                                         nullptr, nullptr, nullptr, bg, 1, 1);
        gemm_tc<128><<<nb, 512, sm128>>>(Fcur, mh + 1*8192, ml + 1*8192, bI,
                                         nullptr, nullptr, nullptr, bh, 1, 1);
        // proto = (S @ W_gate) * g + h_self
        gemm_tc<64><<<nb, 512, sm64>>>(S, Ghi + (size_t)l*4096, Glo + (size_t)l*4096,
                                       nullptr, bg, bh, nullptr, bx, 0, 0);

        // interaction residual chain (3 blocks)
        for (int j = 0; j < 3; j++){
            const float* c1 = ri_b1 + (size_t)(l*3 + j) * FD;
            const float* c2 = ri_b2 + (size_t)(l*3 + j) * FD;
            gemm_tc<128><<<nb, 512, sm128>>>(bx, mh + (3+j)*8192, ml + (3+j)*8192, c1,
                                             nullptr, nullptr, nullptr, bt, 1, 0);
            gemm_tc<128><<<nb, 512, sm128>>>(bt, mh + (6+j)*8192, ml + (6+j)*8192, c2,
                                             nullptr, bx, nullptr, bx, 1, 0);
        }
        // feat2 = F*gvec + ssp(msg)@W_int + b_int
        gemm_tc<128><<<nb, 512, sm128>>>(bx, mh + 2*8192, ml + 2*8192, bN,
                                         nullptr, Fcur, gV, Fnxt, 1, 0);
        // atomic residual chain (2 blocks)
        for (int j = 0; j < 2; j++){
            const float* c1 = ra_b1 + (size_t)(l*2 + j) * FD;
            const float* c2 = ra_b2 + (size_t)(l*2 + j) * FD;
            gemm_tc<128><<<nb, 512, sm128>>>(Fnxt, mh + (9+j)*8192,  ml + (9+j)*8192,  c1,
                                             nullptr, nullptr, nullptr, bt, 1, 0);
            gemm_tc<128><<<nb, 512, sm128>>>(bt,   mh + (11+j)*8192, ml + (11+j)*8192, c2,
                                             nullptr, Fnxt, nullptr, Fnxt, 1, 0);
        }
        // output residual chain (1 block) -> bx
        {
            const float* c1 = ro_b1 + (size_t)l * FD;
            const float* c2 = ro_b2 + (size_t)l * FD;
            gemm_tc<128><<<nb, 512, sm128>>>(Fnxt, mh + 13*8192, ml + 13*8192, c1,
                                             nullptr, nullptr, nullptr, bt, 1, 0);
            gemm_tc<128><<<nb, 512, sm128>>>(bt,   mh + 14*8192, ml + 14*8192, c2,
                                             nullptr, Fnxt, nullptr, bx, 1, 0);
        }
        // E (+)= ssp(bx) @ W_out + b_out
        energy_kernel<<<N / 8, 256>>>(bx, W_out + (size_t)l * FD, b_out + l, E, (l == 0) ? 1 : 0);

        Fcur = Fnxt;
    }

    if (out_size >= N + N * FD){
        cudaMemcpyAsync(outFeat, Fcur, (size_t)N * FD * sizeof(float),
                        cudaMemcpyDeviceToDevice);
    }
}

// round 12
// speedup vs baseline: 2.4414x; 1.4141x over previous
#include <cuda_runtime.h>
#include <cuda_bf16.h>
#include <stdint.h>
#include <math.h>

#define FD 128
#define RD 64
#define NMAX 8192
#define LMAX 5

// ---------------- scratch (no runtime allocation allowed) ----------------
__device__ float g_S [NMAX*RD];
// pre-transposed/split weight images: B[n][k] packed as uint32 (2 bf16 along k)
__device__ uint32_t g_Whi[LMAX*15*8192];
__device__ uint32_t g_Wlo[LMAX*15*8192];
__device__ uint32_t g_Ghi[LMAX*4096];
__device__ uint32_t g_Glo[LMAX*4096];

__device__ __forceinline__ uint32_t smem_u32(const void* p){
    uint32_t a;
    asm("{ .reg .u64 t; cvta.to.shared.u64 t, %1; cvt.u32.u64 %0, t; }" : "=r"(a) : "l"(p));
    return a;
}
__device__ __forceinline__ float sspf(float x){
    return fmaxf(x, 0.0f) + log1pf(__expf(-fabsf(x))) - 0.6931471805599453f;
}
__device__ __forceinline__ uint32_t bits2(__nv_bfloat162 v){
    return *reinterpret_cast<uint32_t*>(&v);
}

#define LDSM_X4(r0,r1,r2,r3,addr) \
    asm volatile("ldmatrix.sync.aligned.m8n8.x4.shared.b16 {%0,%1,%2,%3}, [%4];" \
        : "=r"(r0), "=r"(r1), "=r"(r2), "=r"(r3) : "r"(addr))

#define MMA16816(d, a0,a1,a2,a3, b0,b1) \
    asm volatile("mma.sync.aligned.m16n8k16.row.col.f32.bf16.bf16.f32 " \
        "{%0,%1,%2,%3}, {%4,%5,%6,%7}, {%8,%9}, {%0,%1,%2,%3};" \
        : "+f"((d)[0]), "+f"((d)[1]), "+f"((d)[2]), "+f"((d)[3]) \
        : "r"(a0), "r"(a1), "r"(a2), "r"(a3), "r"(b0), "r"(b1))

#define CP_ASYNC16(saddr, gptr) \
    asm volatile("cp.async.cg.shared.global [%0], [%1], 16;" :: "r"(saddr), "l"(gptr))
#define CP_COMMIT() asm volatile("cp.async.commit_group;" ::: "memory")
#define CP_WAIT0()  asm volatile("cp.async.wait_group 0;" ::: "memory")
#define CP_WAIT1()  asm volatile("cp.async.wait_group 1;" ::: "memory")

// ---------------- helper kernels (unchanged, validated) ----------------
__global__ void zero_kernel(float* __restrict__ p, int n){
    int i = blockIdx.x * blockDim.x + threadIdx.x;
    if (i < n) p[i] = 0.0f;
}

__global__ void scatter_kernel(const float* __restrict__ radial,
                               const int*   __restrict__ idx,
                               float* __restrict__ S, int P){
    int gid = blockIdx.x * blockDim.x + threadIdx.x;
    if (gid >= P * (RD/4)) return;
    int c = gid & 15;
    int p = gid >> 4;
    float4 v = *reinterpret_cast<const float4*>(radial + (size_t)p * RD + c * 4);
    int a0 = idx[p];
    int a1 = idx[P + p];
    atomicAdd(reinterpret_cast<float4*>(S + (size_t)a0 * RD + c * 4), v);
    atomicAdd(reinterpret_cast<float4*>(S + (size_t)a1 * RD + c * 4), v);
}

__global__ void __launch_bounds__(256) prep_weights(
    const float* __restrict__ W_J, const float* __restrict__ W_I,
    const float* __restrict__ W_int,
    const float* __restrict__ ri_W1, const float* __restrict__ ri_W2,
    const float* __restrict__ ra_W1, const float* __restrict__ ra_W2,
    const float* __restrict__ ro_W1, const float* __restrict__ ro_W2,
    const float* __restrict__ W_gate, int L)
{
    int b = blockIdx.x;
    if (b < L * 15){
        int l = b / 15, slot = b % 15;
        const float* W;
        size_t ff = (size_t)FD * FD;
        if      (slot == 0)  W = W_J   + (size_t)l * ff;
        else if (slot == 1)  W = W_I   + (size_t)l * ff;
        else if (slot == 2)  W = W_int + (size_t)l * ff;
        else if (slot <= 5)  W = ri_W1 + (size_t)(l*3 + (slot-3))  * ff;
        else if (slot <= 8)  W = ri_W2 + (size_t)(l*3 + (slot-6))  * ff;
        else if (slot <= 10) W = ra_W1 + (size_t)(l*2 + (slot-9))  * ff;
        else if (slot <= 12) W = ra_W2 + (size_t)(l*2 + (slot-11)) * ff;
        else if (slot == 13) W = ro_W1 + (size_t)l * ff;
        else                 W = ro_W2 + (size_t)l * ff;
        uint32_t* oh = g_Whi + (size_t)b * 8192;
        uint32_t* ol = g_Wlo + (size_t)b * 8192;
        for (int i = threadIdx.x; i < 8192; i += 256){
            int n  = i >> 6;
            int kk = i & 63;
            float a = W[(size_t)(2*kk)   * FD + n];
            float c = W[(size_t)(2*kk+1) * FD + n];
            __nv_bfloat162 h2 = __floats2bfloat162_rn(a, c);
            __nv_bfloat162 l2 = __floats2bfloat162_rn(a - __bfloat162float(h2.x),
                                                      c - __bfloat162float(h2.y));
            oh[i] = bits2(h2);
            ol[i] = bits2(l2);
        }
    } else {
        int l = b - L * 15;
        const float* W = W_gate + (size_t)l * RD * FD;   // [64, 128]
        uint32_t* oh = g_Ghi + (size_t)l * 4096;
        uint32_t* ol = g_Glo + (size_t)l * 4096;
        for (int i = threadIdx.x; i < 4096; i += 256){
            int n  = i >> 5;
            int kk = i & 31;
            float a = W[(size_t)(2*kk)   * FD + n];
            float c = W[(size_t)(2*kk+1) * FD + n];
            __nv_bfloat162 h2 = __floats2bfloat162_rn(a, c);
            __nv_bfloat162 l2 = __floats2bfloat162_rn(a - __bfloat162float(h2.x),
                                                      c - __bfloat162float(h2.y));
            oh[i] = bits2(h2);
            ol[i] = bits2(l2);
        }
    }
}

// ---------------- fused persistent network kernel ----------------
// SMEM map (bytes):
//   A planes  (hi, lo)  : [0, 34816)       rows 64, stride 272, lo at +17408
//   S planes  (hi, lo)  : [34816, 53248)   rows 64, stride 144, lo at +9216
//   B buf0    (hi, lo)  : [53248, 122880)  rows 128, stride 272, lo at +34816
//   B buf1    (hi, lo)  : [122880, 192512)
//   rowsum (64 floats)  : [192512, 192768)
#define OFF_A   0
#define A_LO    17408
#define OFF_S   34816
#define S_LO    9216
#define OFF_B0  53248
#define OFF_B1  122880
#define B_LO    34816
#define OFF_RS  192512
#define SM_TOT  192768

template<int KSTEPS>
__device__ __forceinline__ void mma_tile(
    uint32_t pAh, uint32_t pAl, uint32_t a0o, uint32_t a1o,
    uint32_t pBh, uint32_t pBl, uint32_t bo, float (&acc)[2][2][4])
{
    #pragma unroll
    for (int ks = 0; ks < KSTEPS; ks++){
        const uint32_t kb = ks * 32;
        uint32_t ah[2][4], al[2][4], bh[4], bl[4];
        LDSM_X4(ah[0][0],ah[0][1],ah[0][2],ah[0][3], pAh + a0o + kb);
        LDSM_X4(ah[1][0],ah[1][1],ah[1][2],ah[1][3], pAh + a1o + kb);
        LDSM_X4(al[0][0],al[0][1],al[0][2],al[0][3], pAl + a0o + kb);
        LDSM_X4(al[1][0],al[1][1],al[1][2],al[1][3], pAl + a1o + kb);
        LDSM_X4(bh[0],bh[1],bh[2],bh[3], pBh + bo + kb);
        LDSM_X4(bl[0],bl[1],bl[2],bl[3], pBl + bo + kb);
        #pragma unroll
        for (int mt = 0; mt < 2; mt++)
            #pragma unroll
            for (int nt = 0; nt < 2; nt++){
                MMA16816(acc[mt][nt], ah[mt][0],ah[mt][1],ah[mt][2],ah[mt][3],
                         bh[nt*2], bh[nt*2+1]);
                MMA16816(acc[mt][nt], ah[mt][0],ah[mt][1],ah[mt][2],ah[mt][3],
                         bl[nt*2], bl[nt*2+1]);
                MMA16816(acc[mt][nt], al[mt][0],al[mt][1],al[mt][2],al[mt][3],
                         bh[nt*2], bh[nt*2+1]);
            }
    }
}

__device__ __forceinline__ void stage_w(int l, int slot,
    const uint32_t** hi, const uint32_t** lo, int* ch)
{
    if (slot == 2){
        *hi = g_Ghi + (size_t)l * 4096; *lo = g_Glo + (size_t)l * 4096; *ch = 8;
        return;
    }
    int ps;
    switch (slot){
        case 0:  ps = 0;  break;  case 1:  ps = 1;  break;
        case 3:  ps = 3;  break;  case 5:  ps = 4;  break;  case 7:  ps = 5;  break;
        case 4:  ps = 6;  break;  case 6:  ps = 7;  break;  case 8:  ps = 8;  break;
        case 9:  ps = 2;  break;
        case 10: ps = 9;  break;  case 12: ps = 10; break;
        case 11: ps = 11; break;  case 13: ps = 12; break;
        case 14: ps = 13; break;  default: ps = 14; break;
    }
    size_t o = (size_t)(l * 15 + ps) * 8192;
    *hi = g_Whi + o; *lo = g_Wlo + o; *ch = 16;
}

__global__ void __launch_bounds__(512, 1) fused_net(
    const float* __restrict__ features,
    const float* __restrict__ b_I,  const float* __restrict__ b_J,
    const float* __restrict__ gvec, const float* __restrict__ b_int,
    const float* __restrict__ ri_b1, const float* __restrict__ ri_b2,
    const float* __restrict__ ra_b1, const float* __restrict__ ra_b2,
    const float* __restrict__ ro_b1, const float* __restrict__ ro_b2,
    const float* __restrict__ W_out, const float* __restrict__ b_out,
    float* __restrict__ E, float* __restrict__ outFeat, int L)
{
    extern __shared__ char smem[];
    const uint32_t sb = smem_u32(smem);
    float* rowsum = reinterpret_cast<float*>(smem + OFF_RS);

    const int tid = threadIdx.x, wid = tid >> 5, lane = tid & 31;
    const int wm = wid >> 3, wn = wid & 7;
    const int mat = lane >> 3, r = lane & 7;
    const int g = lane >> 2, c2 = (lane & 3) * 2;
    const int colbase = wn * 16 + c2;          // + nt*8
    const int rowbase = wm * 32 + g;           // + mt*16 + hh*8 (local)
    const int grow0 = blockIdx.x * 64;

    // ldmatrix lane offsets
    uint32_t aoffA[2], aoffS[2];
    #pragma unroll
    for (int mt = 0; mt < 2; mt++){
        int rr = wm*32 + mt*16 + r + ((mat & 1) << 3);
        int kc = ((mat >> 1) << 3) * 2;
        aoffA[mt] = (uint32_t)(rr * 272 + kc);
        aoffS[mt] = (uint32_t)(rr * 144 + kc);
    }
    const uint32_t boff = (uint32_t)((wn*16 + ((mat >> 1) << 3) + r) * 272
                                     + ((mat & 1) << 3) * 2);

    // ---------------- init ----------------
    for (int i = tid; i < 64; i += 512) rowsum[i] = 0.f;

    // register activation buffers (fragment layout)
    float rF[2][2][4], rG[2][2][4], rH[2][2][4], rX[2][2][4];

    // load features -> rF; build A planes = split(ssp(rF))
    #pragma unroll
    for (int mt = 0; mt < 2; mt++)
        #pragma unroll
        for (int hh = 0; hh < 2; hh++){
            int row = rowbase + mt*16 + hh*8;
            #pragma unroll
            for (int nt = 0; nt < 2; nt++){
                float2 v = *reinterpret_cast<const float2*>(
                    features + (size_t)(grow0 + row) * FD + colbase + nt*8);
                rF[mt][nt][hh*2]   = v.x;
                rF[mt][nt][hh*2+1] = v.y;
                float s0 = sspf(v.x), s1 = sspf(v.y);
                __nv_bfloat162 h2 = __floats2bfloat162_rn(s0, s1);
                __nv_bfloat162 l2 = __floats2bfloat162_rn(s0 - __bfloat162float(h2.x),
                                                          s1 - __bfloat162float(h2.y));
                char* p = smem + OFF_A + row * 272 + (colbase + nt*8) * 2;
                *reinterpret_cast<uint32_t*>(p)        = bits2(h2);
                *reinterpret_cast<uint32_t*>(p + A_LO) = bits2(l2);
            }
        }

    // build S planes (once): S tile [64 x 64] fp32 -> bf16 hi/lo, stride 144
    for (int i = tid; i < 64 * 32; i += 512){
        int row = i >> 5, kk = i & 31;
        float2 v = *reinterpret_cast<const float2*>(
            g_S + (size_t)(grow0 + row) * RD + 2 * kk);
        __nv_bfloat162 h2 = __floats2bfloat162_rn(v.x, v.y);
        __nv_bfloat162 l2 = __floats2bfloat162_rn(v.x - __bfloat162float(h2.x),
                                                  v.y - __bfloat162float(h2.y));
        char* p = smem + OFF_S + row * 144 + kk * 4;
        *reinterpret_cast<uint32_t*>(p)        = bits2(h2);
        *reinterpret_cast<uint32_t*>(p + S_LO) = bits2(l2);
    }

    // prefetch stage 0 weights into buf0
    {
        const uint32_t *hi, *lo; int ch;
        stage_w(0, 0, &hi, &lo, &ch);
        uint32_t bBh = sb + OFF_B0, bBl = bBh + B_LO;
        for (int i = tid; i < 128 * ch; i += 512){
            int n = i / ch, c = i - n * ch;
            uint32_t d = (uint32_t)(n * 272 + c * 16);
            CP_ASYNC16(bBh + d, (const uint4*)hi + i);
            CP_ASYNC16(bBl + d, (const uint4*)lo + i);
        }
        CP_COMMIT();
    }

    const int NS = 16 * L;
    for (int s = 0; s < NS; s++){
        const int l = s >> 4, slot = s & 15;

        // prefetch next stage weights into buf (s+1)&1
        if (s + 1 < NS){
            const uint32_t *hi, *lo; int ch;
            stage_w((s+1) >> 4, (s+1) & 15, &hi, &lo, &ch);
            uint32_t base = sb + (((s+1) & 1) ? OFF_B1 : OFF_B0);
            uint32_t bBl2 = base + B_LO;
            for (int i = tid; i < 128 * ch; i += 512){
                int n = i / ch, c = i - n * ch;
                uint32_t d = (uint32_t)(n * 272 + c * 16);
                CP_ASYNC16(base + d, (const uint4*)hi + i);
                CP_ASYNC16(bBl2 + d, (const uint4*)lo + i);
            }
            CP_COMMIT();
            CP_WAIT1();
        } else {
            CP_WAIT0();
        }
        __syncthreads();   // weights for s visible + previous epilogue STS visible

        // ---- mainloop ----
        float acc[2][2][4];
        #pragma unroll
        for (int i = 0; i < 2; i++)
            #pragma unroll
            for (int j = 0; j < 2; j++)
                #pragma unroll
                for (int q = 0; q < 4; q++) acc[i][j][q] = 0.f;

        uint32_t bB = sb + ((s & 1) ? OFF_B1 : OFF_B0);
        if (slot == 2)
            mma_tile<4>(sb + OFF_S, sb + OFF_S + S_LO, aoffS[0], aoffS[1],
                        bB, bB + B_LO, boff, acc);
        else
            mma_tile<8>(sb + OFF_A, sb + OFF_A + A_LO, aoffA[0], aoffA[1],
                        bB, bB + B_LO, boff, acc);

        __syncthreads();   // all LDSM reads done before epilogue STS rewrites A planes

        // ---- epilogue ----
        // bias
        {
            const float* bias = nullptr;
            switch (slot){
                case 0:  bias = b_J   + (size_t)l * FD; break;
                case 1:  bias = b_I   + (size_t)l * FD; break;
                case 2:  break;
                case 3:  bias = ri_b1 + (size_t)(l*3 + 0) * FD; break;
                case 5:  bias = ri_b1 + (size_t)(l*3 + 1) * FD; break;
                case 7:  bias = ri_b1 + (size_t)(l*3 + 2) * FD; break;
                case 4:  bias = ri_b2 + (size_t)(l*3 + 0) * FD; break;
                case 6:  bias = ri_b2 + (size_t)(l*3 + 1) * FD; break;
                case 8:  bias = ri_b2 + (size_t)(l*3 + 2) * FD; break;
                case 9:  bias = b_int + (size_t)l * FD; break;
                case 10: bias = ra_b1 + (size_t)(l*2 + 0) * FD; break;
                case 12: bias = ra_b1 + (size_t)(l*2 + 1) * FD; break;
                case 11: bias = ra_b2 + (size_t)(l*2 + 0) * FD; break;
                case 13: bias = ra_b2 + (size_t)(l*2 + 1) * FD; break;
                case 14: bias = ro_b1 + (size_t)l * FD; break;
                default: bias = ro_b2 + (size_t)l * FD; break;
            }
            if (bias){
                #pragma unroll
                for (int nt = 0; nt < 2; nt++){
                    float2 bv = *reinterpret_cast<const float2*>(bias + colbase + nt*8);
                    #pragma unroll
                    for (int mt = 0; mt < 2; mt++){
                        acc[mt][nt][0] += bv.x; acc[mt][nt][1] += bv.y;
                        acc[mt][nt][2] += bv.x; acc[mt][nt][3] += bv.y;
                    }
                }
            }
        }

        // slot-specific combine + A-plane rebuild
        bool writeA = true;
        float (*src)[2][4] = acc;   // values whose ssp goes into A planes

        if (slot == 0){
            #pragma unroll
            for (int mt = 0; mt < 2; mt++)
                #pragma unroll
                for (int nt = 0; nt < 2; nt++)
                    #pragma unroll
                    for (int q = 0; q < 4; q++) rG[mt][nt][q] = sspf(acc[mt][nt][q]);
            writeA = false;
        } else if (slot == 1){
            #pragma unroll
            for (int mt = 0; mt < 2; mt++)
                #pragma unroll
                for (int nt = 0; nt < 2; nt++)
                    #pragma unroll
                    for (int q = 0; q < 4; q++) rH[mt][nt][q] = sspf(acc[mt][nt][q]);
            writeA = false;
        } else if (slot == 2){
            #pragma unroll
            for (int mt = 0; mt < 2; mt++)
                #pragma unroll
                for (int nt = 0; nt < 2; nt++)
                    #pragma unroll
                    for (int q = 0; q < 4; q++)
                        rX[mt][nt][q] = acc[mt][nt][q] * rG[mt][nt][q] + rH[mt][nt][q];
            src = rX;
        } else if (slot == 4 || slot == 6 || slot == 8){
            #pragma unroll
            for (int mt = 0; mt < 2; mt++)
                #pragma unroll
                for (int nt = 0; nt < 2; nt++)
                    #pragma unroll
                    for (int q = 0; q < 4; q++){
                        rX[mt][nt][q] += acc[mt][nt][q];
                    }
            src = rX;
        } else if (slot == 9){
            const float* gv = gvec + (size_t)l * FD;
            #pragma unroll
            for (int nt = 0; nt < 2; nt++){
                float2 gvv = *reinterpret_cast<const float2*>(gv + colbase + nt*8);
                #pragma unroll
                for (int mt = 0; mt < 2; mt++){
                    rF[mt][nt][0] = fmaf(rF[mt][nt][0], gvv.x, acc[mt][nt][0]);
                    rF[mt][nt][1] = fmaf(rF[mt][nt][1], gvv.y, acc[mt][nt][1]);
                    rF[mt][nt][2] = fmaf(rF[mt][nt][2], gvv.x, acc[mt][nt][2]);
                    rF[mt][nt][3] = fmaf(rF[mt][nt][3], gvv.y, acc[mt][nt][3]);
                }
            }
            src = rF;
        } else if (slot == 11 || slot == 13){
            #pragma unroll
            for (int mt = 0; mt < 2; mt++)
                #pragma unroll
                for (int nt = 0; nt < 2; nt++)
                    #pragma unroll
                    for (int q = 0; q < 4; q++) rF[mt][nt][q] += acc[mt][nt][q];
            src = rF;
        } else if (slot == 15){
            // y = acc + rF ; energy partial; A planes <- ssp(rF) for next module
            const float* wout = W_out + (size_t)l * FD;
            float er[2][2] = {{0.f, 0.f}, {0.f, 0.f}};
            #pragma unroll
            for (int nt = 0; nt < 2; nt++){
                float2 w = *reinterpret_cast<const float2*>(wout + colbase + nt*8);
                #pragma unroll
                for (int mt = 0; mt < 2; mt++)
                    #pragma unroll
                    for (int hh = 0; hh < 2; hh++){
                        float y0 = acc[mt][nt][hh*2]   + rF[mt][nt][hh*2];
                        float y1 = acc[mt][nt][hh*2+1] + rF[mt][nt][hh*2+1];
                        er[mt][hh] += sspf(y0) * w.x + sspf(y1) * w.y;
                    }
            }
            #pragma unroll
            for (int mt = 0; mt < 2; mt++)
                #pragma unroll
                for (int hh = 0; hh < 2; hh++){
                    float v = er[mt][hh];
                    v += __shfl_xor_sync(0xffffffff, v, 1);
                    v += __shfl_xor_sync(0xffffffff, v, 2);
                    if ((lane & 3) == 0)
                        atomicAdd(&rowsum[rowbase + mt*16 + hh*8], v);
                }
            src = rF;
        }
        // slots 3,5,7,10,12,14: src stays acc (t-stages)

        if (writeA){
            #pragma unroll
            for (int mt = 0; mt < 2; mt++)
                #pragma unroll
                for (int hh = 0; hh < 2; hh++){
                    int row = rowbase + mt*16 + hh*8;
                    #pragma unroll
                    for (int nt = 0; nt < 2; nt++){
                        float s0 = sspf(src[mt][nt][hh*2]);
                        float s1 = sspf(src[mt][nt][hh*2+1]);
                        __nv_bfloat162 h2 = __floats2bfloat162_rn(s0, s1);
                        __nv_bfloat162 l2 = __floats2bfloat162_rn(
                            s0 - __bfloat162float(h2.x), s1 - __bfloat162float(h2.y));
                        char* p = smem + OFF_A + row * 272 + (colbase + nt*8) * 2;
                        *reinterpret_cast<uint32_t*>(p)        = bits2(h2);
                        *reinterpret_cast<uint32_t*>(p + A_LO) = bits2(l2);
                    }
                }
        }
    }

    __syncthreads();

    // energies
    if (tid < 64){
        float sb2 = 0.f;
        for (int l = 0; l < L; l++) sb2 += b_out[l];
        E[grow0 + tid] = rowsum[tid] + sb2;
    }
    // final features from rF
    #pragma unroll
    for (int mt = 0; mt < 2; mt++)
        #pragma unroll
        for (int hh = 0; hh < 2; hh++){
            int row = rowbase + mt*16 + hh*8;
            #pragma unroll
            for (int nt = 0; nt < 2; nt++){
                float2 v = make_float2(rF[mt][nt][hh*2], rF[mt][nt][hh*2+1]);
                *reinterpret_cast<float2*>(
                    outFeat + (size_t)(grow0 + row) * FD + colbase + nt*8) = v;
            }
        }
}

// ---------------- launch ----------------
extern "C" void kernel_launch(void* const* d_in, const int* in_sizes, int n_in,
                              void* d_out, int out_size)
{
    const float* features = (const float*)d_in[1];
    const float* radial   = (const float*)d_in[2];
    const int*   idx12    = (const int*)  d_in[3];
    const float* W_I   = (const float*)d_in[4];
    const float* b_I   = (const float*)d_in[5];
    const float* W_J   = (const float*)d_in[6];
    const float* b_J   = (const float*)d_in[7];
    const float* W_gate= (const float*)d_in[8];
    const float* gvec  = (const float*)d_in[9];
    const float* W_int = (const float*)d_in[10];
    const float* b_int = (const float*)d_in[11];
    const float* ri_b1 = (const float*)d_in[13];
    const float* ri_b2 = (const float*)d_in[15];
    const float* ra_b1 = (const float*)d_in[17];
    const float* ra_b2 = (const float*)d_in[19];
    const float* ro_b1 = (const float*)d_in[21];
    const float* ro_b2 = (const float*)d_in[23];
    const float* W_out = (const float*)d_in[24];
    const float* b_out = (const float*)d_in[25];

    const int P = in_sizes[3] / 2;
    const int N = in_sizes[1] / FD;
    const int L = in_sizes[4] / (FD * FD);

    float* S;
    cudaGetSymbolAddress((void**)&S, g_S);

    float* E = (float*)d_out;
    float* outFeat = (float*)d_out + N;

    cudaFuncSetAttribute(fused_net, cudaFuncAttributeMaxDynamicSharedMemorySize, SM_TOT);

    prep_weights<<<L * 15 + L, 256>>>(W_J, W_I, W_int,
        (const float*)d_in[12], (const float*)d_in[14],
        (const float*)d_in[16], (const float*)d_in[18],
        (const float*)d_in[20], (const float*)d_in[22], W_gate, L);
    zero_kernel<<<(N * RD + 255) / 256, 256>>>(S, N * RD);
    scatter_kernel<<<(P * (RD/4) + 255) / 256, 256>>>(radial, idx12, S, P);

    fused_net<<<N / 64, 512, SM_TOT>>>(features,
        b_I, b_J, gvec, b_int, ri_b1, ri_b2, ra_b1, ra_b2, ro_b1, ro_b2,
        W_out, b_out, E, outFeat, L);
}

// round 13
// speedup vs baseline: 3.0165x; 1.2356x over previous
#include <cuda_runtime.h>
#include <cuda_bf16.h>
#include <stdint.h>
#include <math.h>

#define FD 128
#define RD 64
#define NMAX 8192
#define LMAX 5

// ---------------- scratch (no runtime allocation allowed) ----------------
__device__ float g_S [NMAX*RD];
// pre-transposed/split weight images: B[n][k] packed as uint32 (2 bf16 along k)
__device__ uint32_t g_Whi[LMAX*15*8192];
__device__ uint32_t g_Wlo[LMAX*15*8192];
__device__ uint32_t g_Ghi[LMAX*4096];
__device__ uint32_t g_Glo[LMAX*4096];

__device__ __forceinline__ uint32_t smem_u32(const void* p){
    uint32_t a;
    asm("{ .reg .u64 t; cvta.to.shared.u64 t, %1; cvt.u32.u64 %0, t; }" : "=r"(a) : "l"(p));
    return a;
}
// fast shifted softplus: arg of log is in [1,2] -> MUFU LG2 path is accurate
__device__ __forceinline__ float sspf(float x){
    return fmaxf(x, 0.0f) + __logf(1.0f + __expf(-fabsf(x))) - 0.6931471805599453f;
}
__device__ __forceinline__ uint32_t bits2(__nv_bfloat162 v){
    return *reinterpret_cast<uint32_t*>(&v);
}

#define LDSM_X4(r0,r1,r2,r3,addr) \
    asm volatile("ldmatrix.sync.aligned.m8n8.x4.shared.b16 {%0,%1,%2,%3}, [%4];" \
        : "=r"(r0), "=r"(r1), "=r"(r2), "=r"(r3) : "r"(addr))

#define MMA16816(d, a0,a1,a2,a3, b0,b1) \
    asm volatile("mma.sync.aligned.m16n8k16.row.col.f32.bf16.bf16.f32 " \
        "{%0,%1,%2,%3}, {%4,%5,%6,%7}, {%8,%9}, {%0,%1,%2,%3};" \
        : "+f"((d)[0]), "+f"((d)[1]), "+f"((d)[2]), "+f"((d)[3]) \
        : "r"(a0), "r"(a1), "r"(a2), "r"(a3), "r"(b0), "r"(b1))

#define CP_ASYNC16(saddr, gptr) \
    asm volatile("cp.async.cg.shared.global [%0], [%1], 16;" :: "r"(saddr), "l"(gptr))
#define CP_COMMIT() asm volatile("cp.async.commit_group;" ::: "memory")
#define CP_WAIT0()  asm volatile("cp.async.wait_group 0;" ::: "memory")
#define CP_WAIT1()  asm volatile("cp.async.wait_group 1;" ::: "memory")

// ---------------- helper kernels (unchanged, validated) ----------------
__global__ void zero_kernel(float* __restrict__ p, int n){
    int i = blockIdx.x * blockDim.x + threadIdx.x;
    if (i < n) p[i] = 0.0f;
}

__global__ void scatter_kernel(const float* __restrict__ radial,
                               const int*   __restrict__ idx,
                               float* __restrict__ S, int P){
    int gid = blockIdx.x * blockDim.x + threadIdx.x;
    if (gid >= P * (RD/4)) return;
    int c = gid & 15;
    int p = gid >> 4;
    float4 v = *reinterpret_cast<const float4*>(radial + (size_t)p * RD + c * 4);
    int a0 = idx[p];
    int a1 = idx[P + p];
    atomicAdd(reinterpret_cast<float4*>(S + (size_t)a0 * RD + c * 4), v);
    atomicAdd(reinterpret_cast<float4*>(S + (size_t)a1 * RD + c * 4), v);
}

__global__ void __launch_bounds__(256) prep_weights(
    const float* __restrict__ W_J, const float* __restrict__ W_I,
    const float* __restrict__ W_int,
    const float* __restrict__ ri_W1, const float* __restrict__ ri_W2,
    const float* __restrict__ ra_W1, const float* __restrict__ ra_W2,
    const float* __restrict__ ro_W1, const float* __restrict__ ro_W2,
    const float* __restrict__ W_gate, int L)
{
    int b = blockIdx.x;
    if (b < L * 15){
        int l = b / 15, slot = b % 15;
        const float* W;
        size_t ff = (size_t)FD * FD;
        if      (slot == 0)  W = W_J   + (size_t)l * ff;
        else if (slot == 1)  W = W_I   + (size_t)l * ff;
        else if (slot == 2)  W = W_int + (size_t)l * ff;
        else if (slot <= 5)  W = ri_W1 + (size_t)(l*3 + (slot-3))  * ff;
        else if (slot <= 8)  W = ri_W2 + (size_t)(l*3 + (slot-6))  * ff;
        else if (slot <= 10) W = ra_W1 + (size_t)(l*2 + (slot-9))  * ff;
        else if (slot <= 12) W = ra_W2 + (size_t)(l*2 + (slot-11)) * ff;
        else if (slot == 13) W = ro_W1 + (size_t)l * ff;
        else                 W = ro_W2 + (size_t)l * ff;
        uint32_t* oh = g_Whi + (size_t)b * 8192;
        uint32_t* ol = g_Wlo + (size_t)b * 8192;
        for (int i = threadIdx.x; i < 8192; i += 256){
            int n  = i >> 6;
            int kk = i & 63;
            float a = W[(size_t)(2*kk)   * FD + n];
            float c = W[(size_t)(2*kk+1) * FD + n];
            __nv_bfloat162 h2 = __floats2bfloat162_rn(a, c);
            __nv_bfloat162 l2 = __floats2bfloat162_rn(a - __bfloat162float(h2.x),
                                                      c - __bfloat162float(h2.y));
            oh[i] = bits2(h2);
            ol[i] = bits2(l2);
        }
    } else {
        int l = b - L * 15;
        const float* W = W_gate + (size_t)l * RD * FD;   // [64, 128]
        uint32_t* oh = g_Ghi + (size_t)l * 4096;
        uint32_t* ol = g_Glo + (size_t)l * 4096;
        for (int i = threadIdx.x; i < 4096; i += 256){
            int n  = i >> 5;
            int kk = i & 31;
            float a = W[(size_t)(2*kk)   * FD + n];
            float c = W[(size_t)(2*kk+1) * FD + n];
            __nv_bfloat162 h2 = __floats2bfloat162_rn(a, c);
            __nv_bfloat162 l2 = __floats2bfloat162_rn(a - __bfloat162float(h2.x),
                                                      c - __bfloat162float(h2.y));
            oh[i] = bits2(h2);
            ol[i] = bits2(l2);
        }
    }
}

// ---------------- fused persistent network kernel ----------------
// SMEM map (bytes):
//   A buf0 (hi, lo) : [0, 34816)        rows 64, stride 272, lo at +17408
//   A buf1 (hi, lo) : [34816, 69632)
//   S planes        : [69632, 88064)    rows 64, stride 144, lo at +9216
//   B buf0 (hi, lo) : [88064, 157696)   rows 128, stride 272, lo at +34816
//   B buf1 (hi, lo) : [157696, 227328)
//   rowsum          : [227328, 227584)
#define OFF_A0  0
#define OFF_A1  34816
#define A_LO    17408
#define OFF_S   69632
#define S_LO    9216
#define OFF_B0  88064
#define OFF_B1  157696
#define B_LO    34816
#define OFF_RS  227328
#define SM_TOT  227584

template<int KSTEPS>
__device__ __forceinline__ void mma_tile(
    uint32_t pAh, uint32_t pAl, uint32_t a0o, uint32_t a1o,
    uint32_t pBh, uint32_t pBl, uint32_t bo, float (&acc)[2][2][4])
{
    #pragma unroll
    for (int ks = 0; ks < KSTEPS; ks++){
        const uint32_t kb = ks * 32;
        uint32_t ah[2][4], al[2][4], bh[4], bl[4];
        LDSM_X4(ah[0][0],ah[0][1],ah[0][2],ah[0][3], pAh + a0o + kb);
        LDSM_X4(ah[1][0],ah[1][1],ah[1][2],ah[1][3], pAh + a1o + kb);
        LDSM_X4(al[0][0],al[0][1],al[0][2],al[0][3], pAl + a0o + kb);
        LDSM_X4(al[1][0],al[1][1],al[1][2],al[1][3], pAl + a1o + kb);
        LDSM_X4(bh[0],bh[1],bh[2],bh[3], pBh + bo + kb);
        LDSM_X4(bl[0],bl[1],bl[2],bl[3], pBl + bo + kb);
        #pragma unroll
        for (int mt = 0; mt < 2; mt++)
            #pragma unroll
            for (int nt = 0; nt < 2; nt++){
                MMA16816(acc[mt][nt], ah[mt][0],ah[mt][1],ah[mt][2],ah[mt][3],
                         bh[nt*2], bh[nt*2+1]);
                MMA16816(acc[mt][nt], ah[mt][0],ah[mt][1],ah[mt][2],ah[mt][3],
                         bl[nt*2], bl[nt*2+1]);
                MMA16816(acc[mt][nt], al[mt][0],al[mt][1],al[mt][2],al[mt][3],
                         bh[nt*2], bh[nt*2+1]);
            }
    }
}

__device__ __forceinline__ void stage_w(int l, int slot,
    const uint32_t** hi, const uint32_t** lo, int* ch)
{
    if (slot == 2){
        *hi = g_Ghi + (size_t)l * 4096; *lo = g_Glo + (size_t)l * 4096; *ch = 8;
        return;
    }
    int ps;
    switch (slot){
        case 0:  ps = 0;  break;  case 1:  ps = 1;  break;
        case 3:  ps = 3;  break;  case 5:  ps = 4;  break;  case 7:  ps = 5;  break;
        case 4:  ps = 6;  break;  case 6:  ps = 7;  break;  case 8:  ps = 8;  break;
        case 9:  ps = 2;  break;
        case 10: ps = 9;  break;  case 12: ps = 10; break;
        case 11: ps = 11; break;  case 13: ps = 12; break;
        case 14: ps = 13; break;  default: ps = 14; break;
    }
    size_t o = (size_t)(l * 15 + ps) * 8192;
    *hi = g_Whi + o; *lo = g_Wlo + o; *ch = 16;
}

__global__ void __launch_bounds__(512, 1) fused_net(
    const float* __restrict__ features,
    const float* __restrict__ b_I,  const float* __restrict__ b_J,
    const float* __restrict__ gvec, const float* __restrict__ b_int,
    const float* __restrict__ ri_b1, const float* __restrict__ ri_b2,
    const float* __restrict__ ra_b1, const float* __restrict__ ra_b2,
    const float* __restrict__ ro_b1, const float* __restrict__ ro_b2,
    const float* __restrict__ W_out, const float* __restrict__ b_out,
    float* __restrict__ E, float* __restrict__ outFeat, int L)
{
    extern __shared__ char smem[];
    const uint32_t sb = smem_u32(smem);
    float* rowsum = reinterpret_cast<float*>(smem + OFF_RS);

    const int tid = threadIdx.x, wid = tid >> 5, lane = tid & 31;
    const int wm = wid >> 3, wn = wid & 7;
    const int mat = lane >> 3, r = lane & 7;
    const int g = lane >> 2, c2 = (lane & 3) * 2;
    const int colbase = wn * 16 + c2;          // + nt*8
    const int rowbase = wm * 32 + g;           // + mt*16 + hh*8 (local)
    const int grow0 = blockIdx.x * 64;

    // ldmatrix lane offsets
    uint32_t aoffA[2], aoffS[2];
    #pragma unroll
    for (int mt = 0; mt < 2; mt++){
        int rr = wm*32 + mt*16 + r + ((mat & 1) << 3);
        int kc = ((mat >> 1) << 3) * 2;
        aoffA[mt] = (uint32_t)(rr * 272 + kc);
        aoffS[mt] = (uint32_t)(rr * 144 + kc);
    }
    const uint32_t boff = (uint32_t)((wn*16 + ((mat >> 1) << 3) + r) * 272
                                     + ((mat & 1) << 3) * 2);

    // ---------------- init ----------------
    for (int i = tid; i < 64; i += 512) rowsum[i] = 0.f;

    // register activation buffers (fragment layout)
    float rF[2][2][4], rG[2][2][4], rH[2][2][4], rX[2][2][4];

    // load features -> rF; build A buf0 = split(ssp(rF))
    #pragma unroll
    for (int mt = 0; mt < 2; mt++)
        #pragma unroll
        for (int hh = 0; hh < 2; hh++){
            int row = rowbase + mt*16 + hh*8;
            #pragma unroll
            for (int nt = 0; nt < 2; nt++){
                float2 v = *reinterpret_cast<const float2*>(
                    features + (size_t)(grow0 + row) * FD + colbase + nt*8);
                rF[mt][nt][hh*2]   = v.x;
                rF[mt][nt][hh*2+1] = v.y;
                float s0 = sspf(v.x), s1 = sspf(v.y);
                __nv_bfloat162 h2 = __floats2bfloat162_rn(s0, s1);
                __nv_bfloat162 l2 = __floats2bfloat162_rn(s0 - __bfloat162float(h2.x),
                                                          s1 - __bfloat162float(h2.y));
                char* p = smem + OFF_A0 + row * 272 + (colbase + nt*8) * 2;
                *reinterpret_cast<uint32_t*>(p)        = bits2(h2);
                *reinterpret_cast<uint32_t*>(p + A_LO) = bits2(l2);
            }
        }

    // build S planes (once): S tile [64 x 64] fp32 -> bf16 hi/lo, stride 144
    for (int i = tid; i < 64 * 32; i += 512){
        int row = i >> 5, kk = i & 31;
        float2 v = *reinterpret_cast<const float2*>(
            g_S + (size_t)(grow0 + row) * RD + 2 * kk);
        __nv_bfloat162 h2 = __floats2bfloat162_rn(v.x, v.y);
        __nv_bfloat162 l2 = __floats2bfloat162_rn(v.x - __bfloat162float(h2.x),
                                                  v.y - __bfloat162float(h2.y));
        char* p = smem + OFF_S + row * 144 + kk * 4;
        *reinterpret_cast<uint32_t*>(p)        = bits2(h2);
        *reinterpret_cast<uint32_t*>(p + S_LO) = bits2(l2);
    }

    // prefetch stage 0 weights into buf0
    {
        const uint32_t *hi, *lo; int ch;
        stage_w(0, 0, &hi, &lo, &ch);
        uint32_t bBh = sb + OFF_B0, bBl = bBh + B_LO;
        for (int i = tid; i < 128 * ch; i += 512){
            int n = i / ch, c = i - n * ch;
            uint32_t d = (uint32_t)(n * 272 + c * 16);
            CP_ASYNC16(bBh + d, (const uint4*)hi + i);
            CP_ASYNC16(bBl + d, (const uint4*)lo + i);
        }
        CP_COMMIT();
    }

    int curA = 0;                              // A read buffer for current stage
    const int NS = 16 * L;
    for (int s = 0; s < NS; s++){
        const int l = s >> 4, slot = s & 15;

        // prefetch next stage weights into B buf (s+1)&1
        if (s + 1 < NS){
            const uint32_t *hi, *lo; int ch;
            stage_w((s+1) >> 4, (s+1) & 15, &hi, &lo, &ch);
            uint32_t base = sb + (((s+1) & 1) ? OFF_B1 : OFF_B0);
            uint32_t bBl2 = base + B_LO;
            for (int i = tid; i < 128 * ch; i += 512){
                int n = i / ch, c = i - n * ch;
                uint32_t d = (uint32_t)(n * 272 + c * 16);
                CP_ASYNC16(base + d, (const uint4*)hi + i);
                CP_ASYNC16(bBl2 + d, (const uint4*)lo + i);
            }
            CP_COMMIT();
            CP_WAIT1();
        } else {
            CP_WAIT0();
        }

        // hoist per-stage column vectors (LDG latency hides under MMA)
        float2 bv[2] = {{0.f,0.f},{0.f,0.f}};
        float2 xv[2] = {{0.f,0.f},{0.f,0.f}};   // gvec (slot 9) or W_out (slot 15)
        {
            const float* bias = nullptr;
            switch (slot){
                case 0:  bias = b_J   + (size_t)l * FD; break;
                case 1:  bias = b_I   + (size_t)l * FD; break;
                case 2:  break;
                case 3:  bias = ri_b1 + (size_t)(l*3 + 0) * FD; break;
                case 5:  bias = ri_b1 + (size_t)(l*3 + 1) * FD; break;
                case 7:  bias = ri_b1 + (size_t)(l*3 + 2) * FD; break;
                case 4:  bias = ri_b2 + (size_t)(l*3 + 0) * FD; break;
                case 6:  bias = ri_b2 + (size_t)(l*3 + 1) * FD; break;
                case 8:  bias = ri_b2 + (size_t)(l*3 + 2) * FD; break;
                case 9:  bias = b_int + (size_t)l * FD; break;
                case 10: bias = ra_b1 + (size_t)(l*2 + 0) * FD; break;
                case 12: bias = ra_b1 + (size_t)(l*2 + 1) * FD; break;
                case 11: bias = ra_b2 + (size_t)(l*2 + 0) * FD; break;
                case 13: bias = ra_b2 + (size_t)(l*2 + 1) * FD; break;
                case 14: bias = ro_b1 + (size_t)l * FD; break;
                default: bias = ro_b2 + (size_t)l * FD; break;
            }
            if (bias){
                bv[0] = *reinterpret_cast<const float2*>(bias + colbase);
                bv[1] = *reinterpret_cast<const float2*>(bias + colbase + 8);
            }
            if (slot == 9){
                const float* gv = gvec + (size_t)l * FD;
                xv[0] = *reinterpret_cast<const float2*>(gv + colbase);
                xv[1] = *reinterpret_cast<const float2*>(gv + colbase + 8);
            } else if (slot == 15){
                const float* wo = W_out + (size_t)l * FD;
                xv[0] = *reinterpret_cast<const float2*>(wo + colbase);
                xv[1] = *reinterpret_cast<const float2*>(wo + colbase + 8);
            }
        }

        __syncthreads();   // B[s] arrived everywhere + prev epilogue STS visible

        // ---- mainloop ----
        float acc[2][2][4];
        #pragma unroll
        for (int i = 0; i < 2; i++)
            #pragma unroll
            for (int j = 0; j < 2; j++)
                #pragma unroll
                for (int q = 0; q < 4; q++) acc[i][j][q] = 0.f;

        uint32_t bB = sb + ((s & 1) ? OFF_B1 : OFF_B0);
        uint32_t aBase = sb + (curA ? OFF_A1 : OFF_A0);
        if (slot == 2)
            mma_tile<4>(sb + OFF_S, sb + OFF_S + S_LO, aoffS[0], aoffS[1],
                        bB, bB + B_LO, boff, acc);
        else
            mma_tile<8>(aBase, aBase + A_LO, aoffA[0], aoffA[1],
                        bB, bB + B_LO, boff, acc);

        // ---- epilogue (no barrier: writes go to the OTHER A buffer) ----
        #pragma unroll
        for (int nt = 0; nt < 2; nt++)
            #pragma unroll
            for (int mt = 0; mt < 2; mt++){
                acc[mt][nt][0] += bv[nt].x; acc[mt][nt][1] += bv[nt].y;
                acc[mt][nt][2] += bv[nt].x; acc[mt][nt][3] += bv[nt].y;
            }

        bool writeA = true;
        float (*src)[2][4] = acc;

        if (slot == 0){
            #pragma unroll
            for (int mt = 0; mt < 2; mt++)
                #pragma unroll
                for (int nt = 0; nt < 2; nt++)
                    #pragma unroll
                    for (int q = 0; q < 4; q++) rG[mt][nt][q] = sspf(acc[mt][nt][q]);
            writeA = false;
        } else if (slot == 1){
            #pragma unroll
            for (int mt = 0; mt < 2; mt++)
                #pragma unroll
                for (int nt = 0; nt < 2; nt++)
                    #pragma unroll
                    for (int q = 0; q < 4; q++) rH[mt][nt][q] = sspf(acc[mt][nt][q]);
            writeA = false;
        } else if (slot == 2){
            #pragma unroll
            for (int mt = 0; mt < 2; mt++)
                #pragma unroll
                for (int nt = 0; nt < 2; nt++)
                    #pragma unroll
                    for (int q = 0; q < 4; q++)
                        rX[mt][nt][q] = acc[mt][nt][q] * rG[mt][nt][q] + rH[mt][nt][q];
            src = rX;
        } else if (slot == 4 || slot == 6 || slot == 8){
            #pragma unroll
            for (int mt = 0; mt < 2; mt++)
                #pragma unroll
                for (int nt = 0; nt < 2; nt++)
                    #pragma unroll
                    for (int q = 0; q < 4; q++) rX[mt][nt][q] += acc[mt][nt][q];
            src = rX;
        } else if (slot == 9){
            #pragma unroll
            for (int nt = 0; nt < 2; nt++)
                #pragma unroll
                for (int mt = 0; mt < 2; mt++){
                    rF[mt][nt][0] = fmaf(rF[mt][nt][0], xv[nt].x, acc[mt][nt][0]);
                    rF[mt][nt][1] = fmaf(rF[mt][nt][1], xv[nt].y, acc[mt][nt][1]);
                    rF[mt][nt][2] = fmaf(rF[mt][nt][2], xv[nt].x, acc[mt][nt][2]);
                    rF[mt][nt][3] = fmaf(rF[mt][nt][3], xv[nt].y, acc[mt][nt][3]);
                }
            src = rF;
        } else if (slot == 11 || slot == 13){
            #pragma unroll
            for (int mt = 0; mt < 2; mt++)
                #pragma unroll
                for (int nt = 0; nt < 2; nt++)
                    #pragma unroll
                    for (int q = 0; q < 4; q++) rF[mt][nt][q] += acc[mt][nt][q];
            src = rF;
        } else if (slot == 15){
            float er[2][2] = {{0.f, 0.f}, {0.f, 0.f}};
            #pragma unroll
            for (int nt = 0; nt < 2; nt++){
                #pragma unroll
                for (int mt = 0; mt < 2; mt++)
                    #pragma unroll
                    for (int hh = 0; hh < 2; hh++){
                        float y0 = acc[mt][nt][hh*2]   + rF[mt][nt][hh*2];
                        float y1 = acc[mt][nt][hh*2+1] + rF[mt][nt][hh*2+1];
                        er[mt][hh] += sspf(y0) * xv[nt].x + sspf(y1) * xv[nt].y;
                    }
            }
            #pragma unroll
            for (int mt = 0; mt < 2; mt++)
                #pragma unroll
                for (int hh = 0; hh < 2; hh++){
                    float v = er[mt][hh];
                    v += __shfl_xor_sync(0xffffffff, v, 1);
                    v += __shfl_xor_sync(0xffffffff, v, 2);
                    if ((lane & 3) == 0)
                        atomicAdd(&rowsum[rowbase + mt*16 + hh*8], v);
                }
            src = rF;
        }
        // slots 3,5,7,10,12,14: src stays acc (t-stages)

        if (writeA){
            char* dst = smem + (curA ? OFF_A0 : OFF_A1);   // write the OTHER buffer
            #pragma unroll
            for (int mt = 0; mt < 2; mt++)
                #pragma unroll
                for (int hh = 0; hh < 2; hh++){
                    int row = rowbase + mt*16 + hh*8;
                    #pragma unroll
                    for (int nt = 0; nt < 2; nt++){
                        float s0 = sspf(src[mt][nt][hh*2]);
                        float s1 = sspf(src[mt][nt][hh*2+1]);
                        __nv_bfloat162 h2 = __floats2bfloat162_rn(s0, s1);
                        __nv_bfloat162 l2 = __floats2bfloat162_rn(
                            s0 - __bfloat162float(h2.x), s1 - __bfloat162float(h2.y));
                        char* p = dst + row * 272 + (colbase + nt*8) * 2;
                        *reinterpret_cast<uint32_t*>(p)        = bits2(h2);
                        *reinterpret_cast<uint32_t*>(p + A_LO) = bits2(l2);
                    }
                }
            curA ^= 1;
        }
    }

    __syncthreads();

    // energies
    if (tid < 64){
        float sb2 = 0.f;
        for (int l = 0; l < L; l++) sb2 += b_out[l];
        E[grow0 + tid] = rowsum[tid] + sb2;
    }
    // final features from rF
    #pragma unroll
    for (int mt = 0; mt < 2; mt++)
        #pragma unroll
        for (int hh = 0; hh < 2; hh++){
            int row = rowbase + mt*16 + hh*8;
            #pragma unroll
            for (int nt = 0; nt < 2; nt++){
                float2 v = make_float2(rF[mt][nt][hh*2], rF[mt][nt][hh*2+1]);
                *reinterpret_cast<float2*>(
                    outFeat + (size_t)(grow0 + row) * FD + colbase + nt*8) = v;
            }
        }
}

// ---------------- launch ----------------
extern "C" void kernel_launch(void* const* d_in, const int* in_sizes, int n_in,
                              void* d_out, int out_size)
{
    const float* features = (const float*)d_in[1];
    const float* radial   = (const float*)d_in[2];
    const int*   idx12    = (const int*)  d_in[3];
    const float* W_I   = (const float*)d_in[4];
    const float* b_I   = (const float*)d_in[5];
    const float* W_J   = (const float*)d_in[6];
    const float* b_J   = (const float*)d_in[7];
    const float* W_gate= (const float*)d_in[8];
    const float* gvec  = (const float*)d_in[9];
    const float* W_int = (const float*)d_in[10];
    const float* b_int = (const float*)d_in[11];
    const float* ri_b1 = (const float*)d_in[13];
    const float* ri_b2 = (const float*)d_in[15];
    const float* ra_b1 = (const float*)d_in[17];
    const float* ra_b2 = (const float*)d_in[19];
    const float* ro_b1 = (const float*)d_in[21];
    const float* ro_b2 = (const float*)d_in[23];
    const float* W_out = (const float*)d_in[24];
    const float* b_out = (const float*)d_in[25];

    const int P = in_sizes[3] / 2;
    const int N = in_sizes[1] / FD;
    const int L = in_sizes[4] / (FD * FD);

    float* S;
    cudaGetSymbolAddress((void**)&S, g_S);

    float* E = (float*)d_out;
    float* outFeat = (float*)d_out + N;

    cudaFuncSetAttribute(fused_net, cudaFuncAttributeMaxDynamicSharedMemorySize, SM_TOT);

    prep_weights<<<L * 15 + L, 256>>>(W_J, W_I, W_int,
        (const float*)d_in[12], (const float*)d_in[14],
        (const float*)d_in[16], (const float*)d_in[18],
        (const float*)d_in[20], (const float*)d_in[22], W_gate, L);
    zero_kernel<<<(N * RD + 255) / 256, 256>>>(S, N * RD);
    scatter_kernel<<<(P * (RD/4) + 255) / 256, 256>>>(radial, idx12, S, P);

    fused_net<<<N / 64, 512, SM_TOT>>>(features,
        b_I, b_J, gvec, b_int, ri_b1, ri_b2, ra_b1, ra_b2, ro_b1, ro_b2,
        W_out, b_out, E, outFeat, L);
}